// round 1
// baseline (speedup 1.0000x reference)
#include <cuda_runtime.h>
#include <math.h>

#define B_SZ   8192
#define LEADS  12
#define FIN    512
#define HID    256
#define E3     768
#define MROWS  (B_SZ * LEADS)   // 98304

// ---------------- static scratch (no allocation allowed) ----------------
__device__ float g_A[LEADS * LEADS];
__device__ float g_wInT[HID * E3];     // in_proj_w transposed -> [256,768]
__device__ float g_wOutT[HID * HID];   // out_proj_w transposed -> [256,256]
__device__ float g_qkv[(size_t)MROWS * E3];   // 288 MB
__device__ float g_buf1[(size_t)MROWS * HID]; // 96 MB
__device__ float g_buf2[(size_t)MROWS * HID];
__device__ float g_buf3[(size_t)MROWS * HID];

// ---------------- A_norm init (12x12 GCN adjacency) ----------------
__global__ void k_init_A() {
    if (threadIdx.x != 0 || blockIdx.x != 0) return;
    const int ci[18] = {0,0,1,0,1,2,0,1,1,2,6,7,8,9,10,0,1,2};
    const int cj[18] = {1,2,2,3,3,3,4,4,5,5,7,8,9,10,11,6,9,11};
    float A[12][12];
    for (int i = 0; i < 12; i++)
        for (int j = 0; j < 12; j++) A[i][j] = (i == j) ? 1.0f : 0.0f;
    for (int e = 0; e < 18; e++) { A[ci[e]][cj[e]] = 1.0f; A[cj[e]][ci[e]] = 1.0f; }
    float dinv[12];
    for (int i = 0; i < 12; i++) {
        float s = 0.0f;
        for (int j = 0; j < 12; j++) s += A[i][j];
        dinv[i] = 1.0f / sqrtf(s);
    }
    for (int i = 0; i < 12; i++)
        for (int j = 0; j < 12; j++) g_A[i * 12 + j] = dinv[i] * A[i][j] * dinv[j];
}

// ---------------- small weight transpose ----------------
__global__ void k_transpose(const float* __restrict__ src, float* __restrict__ dst,
                            int rows, int cols) {
    int idx = blockIdx.x * blockDim.x + threadIdx.x;
    if (idx >= rows * cols) return;
    int r = idx / cols, c = idx % cols;
    dst[c * rows + r] = src[idx];
}

// ---------------- SGEMM: C = A[MxK] @ B[KxN] (+bias) ----------------
// Tile 128x64, BK=16, 256 threads, 8x4 register blocking.
template <bool BIAS>
__global__ __launch_bounds__(256) void k_sgemm(
    const float* __restrict__ A, const float* __restrict__ B,
    const float* __restrict__ bias, float* __restrict__ C,
    int M, int N, int K)
{
    const int BM = 128, BN = 64, BK = 16;
    __shared__ float As[BK][BM];
    __shared__ float Bs[BK][BN];

    const int tid  = threadIdx.x;
    const int row0 = blockIdx.y * BM;
    const int col0 = blockIdx.x * BN;
    const int tx = tid & 15;   // 16 col-groups of 4
    const int ty = tid >> 4;   // 16 row-groups of 8

    float acc[8][4];
#pragma unroll
    for (int r = 0; r < 8; r++)
#pragma unroll
        for (int c = 0; c < 4; c++) acc[r][c] = 0.0f;

    const int bk = tid >> 4;          // B-load: k row
    const int bc = (tid & 15) * 4;    // B-load: col offset

    for (int k0 = 0; k0 < K; k0 += BK) {
        // load A tile (128x16), 2 float4 per thread, store transposed
#pragma unroll
        for (int i = 0; i < 2; i++) {
            int idx = tid * 2 + i;          // 0..511
            int r   = idx >> 2;             // 0..127
            int kk4 = (idx & 3) * 4;        // 0,4,8,12
            float4 v = *(const float4*)(A + (size_t)(row0 + r) * K + k0 + kk4);
            As[kk4 + 0][r] = v.x; As[kk4 + 1][r] = v.y;
            As[kk4 + 2][r] = v.z; As[kk4 + 3][r] = v.w;
        }
        // load B tile (16x64), 1 float4 per thread
        {
            float4 v = *(const float4*)(B + (size_t)(k0 + bk) * N + col0 + bc);
            *(float4*)&Bs[bk][bc] = v;
        }
        __syncthreads();

#pragma unroll
        for (int kk = 0; kk < BK; kk++) {
            float4 a0 = *(const float4*)&As[kk][ty * 8];
            float4 a1 = *(const float4*)&As[kk][ty * 8 + 4];
            float4 b  = *(const float4*)&Bs[kk][tx * 4];
            float av[8] = {a0.x, a0.y, a0.z, a0.w, a1.x, a1.y, a1.z, a1.w};
            float bv[4] = {b.x, b.y, b.z, b.w};
#pragma unroll
            for (int r = 0; r < 8; r++)
#pragma unroll
                for (int c = 0; c < 4; c++)
                    acc[r][c] += av[r] * bv[c];
        }
        __syncthreads();
    }

    float bf[4] = {0.f, 0.f, 0.f, 0.f};
    if (BIAS) {
#pragma unroll
        for (int c = 0; c < 4; c++) bf[c] = bias[col0 + tx * 4 + c];
    }
#pragma unroll
    for (int r = 0; r < 8; r++) {
        float4 o;
        o.x = acc[r][0] + bf[0]; o.y = acc[r][1] + bf[1];
        o.z = acc[r][2] + bf[2]; o.w = acc[r][3] + bf[3];
        *(float4*)(C + (size_t)(row0 + ty * 8 + r) * N + col0 + tx * 4) = o;
    }
}

// ---------------- lead-mix: out[b,i,f] = (relu)(sum_j A[i,j] T[b,j,f] + bias[f]) ----
template <bool RELU>
__global__ __launch_bounds__(256) void k_mix(
    const float* __restrict__ T, const float* __restrict__ bias,
    float* __restrict__ out)
{
    int b = blockIdx.x, f = threadIdx.x;
    float t[LEADS];
#pragma unroll
    for (int j = 0; j < LEADS; j++)
        t[j] = T[((size_t)b * LEADS + j) * HID + f];
    float bv = bias[f];
#pragma unroll
    for (int i = 0; i < LEADS; i++) {
        float acc = bv;
#pragma unroll
        for (int j = 0; j < LEADS; j++) acc += g_A[i * 12 + j] * t[j];
        if (RELU) acc = fmaxf(acc, 0.0f);
        out[((size_t)b * LEADS + i) * HID + f] = acc;
    }
}

// ---------------- attention: one block per batch, one warp per head ----------------
__global__ __launch_bounds__(128) void k_attn(const float* __restrict__ qkv,
                                              float* __restrict__ o)
{
    __shared__ float sq[4][12 * 64];
    __shared__ float sk[4][12 * 64];
    __shared__ float sv[4][12 * 64];
    __shared__ float ss[4][12][12];

    int b    = blockIdx.x;
    int w    = threadIdx.x >> 5;   // head
    int lane = threadIdx.x & 31;
    const float* base = qkv + (size_t)b * LEADS * E3;

    for (int idx = lane; idx < 768; idx += 32) {
        int s = idx >> 6, d = idx & 63;
        sq[w][idx] = base[s * E3 +       w * 64 + d];
        sk[w][idx] = base[s * E3 + 256 + w * 64 + d];
        sv[w][idx] = base[s * E3 + 512 + w * 64 + d];
    }
    __syncwarp();

    for (int st = lane; st < 144; st += 32) {
        int s = st / 12, t = st % 12;
        float acc = 0.0f;
#pragma unroll
        for (int d = 0; d < 64; d++) acc += sq[w][s * 64 + d] * sk[w][t * 64 + d];
        ss[w][s][t] = acc * 0.125f;   // 1/sqrt(64)
    }
    __syncwarp();

    if (lane < 12) {
        float mx = -1e30f;
        for (int t = 0; t < 12; t++) mx = fmaxf(mx, ss[w][lane][t]);
        float e[12], sum = 0.0f;
        for (int t = 0; t < 12; t++) { e[t] = expf(ss[w][lane][t] - mx); sum += e[t]; }
        float inv = 1.0f / sum;
        for (int t = 0; t < 12; t++) ss[w][lane][t] = e[t] * inv;
    }
    __syncwarp();

    for (int idx = lane; idx < 768; idx += 32) {
        int s = idx >> 6, d = idx & 63;
        float acc = 0.0f;
#pragma unroll
        for (int t = 0; t < 12; t++) acc += ss[w][s][t] * sv[w][t * 64 + d];
        o[((size_t)b * LEADS + s) * HID + w * 64 + d] = acc;
    }
}

// ---------------- residual + LayerNorm: one warp per row ----------------
__global__ __launch_bounds__(256) void k_ln(
    const float* __restrict__ h, const float* __restrict__ a,
    const float* __restrict__ g, const float* __restrict__ bta,
    float* __restrict__ out)
{
    int row  = blockIdx.x * 8 + (threadIdx.x >> 5);
    int lane = threadIdx.x & 31;
    const float* hp = h + (size_t)row * HID;
    const float* ap = a + (size_t)row * HID;

    float v[8];
    float sum = 0.0f;
#pragma unroll
    for (int j = 0; j < 8; j++) {
        int c = lane + 32 * j;
        v[j] = hp[c] + ap[c];
        sum += v[j];
    }
#pragma unroll
    for (int off = 16; off; off >>= 1) sum += __shfl_xor_sync(0xFFFFFFFFu, sum, off);
    float mu = sum * (1.0f / 256.0f);

    float vs = 0.0f;
#pragma unroll
    for (int j = 0; j < 8; j++) { float d = v[j] - mu; vs += d * d; }
#pragma unroll
    for (int off = 16; off; off >>= 1) vs += __shfl_xor_sync(0xFFFFFFFFu, vs, off);
    float rs = rsqrtf(vs * (1.0f / 256.0f) + 1e-5f);

#pragma unroll
    for (int j = 0; j < 8; j++) {
        int c = lane + 32 * j;
        out[(size_t)row * HID + c] = (v[j] - mu) * rs * g[c] + bta[c];
    }
}

// ---------------- final: gcn3 lead-mix + pooling (softmax-weighted + max) ------
__global__ __launch_bounds__(256) void k_final(
    const float* __restrict__ T3, const float* __restrict__ b3,
    float* __restrict__ out)
{
    __shared__ float red[12][8];
    __shared__ float sw[12];
    int b = blockIdx.x, f = threadIdx.x;
    int lane = f & 31, wid = f >> 5;

    float t[LEADS];
#pragma unroll
    for (int j = 0; j < LEADS; j++)
        t[j] = T3[((size_t)b * LEADS + j) * HID + f];

    float bias = b3[f];
    float h3[LEADS];
#pragma unroll
    for (int i = 0; i < LEADS; i++) {
        float acc = bias;
#pragma unroll
        for (int j = 0; j < LEADS; j++) acc += g_A[i * 12 + j] * t[j];
        h3[i] = acc;
    }

    // per-lead mean over 256 features
#pragma unroll
    for (int i = 0; i < LEADS; i++) {
        float s = h3[i];
#pragma unroll
        for (int off = 16; off; off >>= 1) s += __shfl_xor_sync(0xFFFFFFFFu, s, off);
        if (lane == 0) red[i][wid] = s;
    }
    __syncthreads();
    if (f < 12) {
        float s = 0.0f;
        for (int w = 0; w < 8; w++) s += red[f][w];
        sw[f] = s * (1.0f / 256.0f);
    }
    __syncthreads();
    if (f == 0) {
        float mx = -1e30f;
        for (int i = 0; i < 12; i++) mx = fmaxf(mx, sw[i]);
        float e[12], sum = 0.0f;
        for (int i = 0; i < 12; i++) { e[i] = expf(sw[i] - mx); sum += e[i]; }
        float inv = 1.0f / sum;
        for (int i = 0; i < 12; i++) sw[i] = e[i] * inv;
    }
    __syncthreads();

    float ws = 0.0f, mx = -1e30f;
#pragma unroll
    for (int i = 0; i < LEADS; i++) {
        ws += h3[i] * sw[i];
        mx = fmaxf(mx, h3[i]);
    }
    out[(size_t)b * 512 + f]       = ws;
    out[(size_t)b * 512 + 256 + f] = mx;
}

// ---------------- launcher ----------------
extern "C" void kernel_launch(void* const* d_in, const int* in_sizes, int n_in,
                              void* d_out, int out_size)
{
    const float* x    = (const float*)d_in[0];
    const float* W1   = (const float*)d_in[1];
    const float* b1   = (const float*)d_in[2];
    const float* W2   = (const float*)d_in[3];
    const float* b2   = (const float*)d_in[4];
    const float* W3   = (const float*)d_in[5];
    const float* b3   = (const float*)d_in[6];
    const float* inW  = (const float*)d_in[7];
    const float* inB  = (const float*)d_in[8];
    const float* outW = (const float*)d_in[9];
    const float* outB = (const float*)d_in[10];
    const float* lng  = (const float*)d_in[11];
    const float* lnb  = (const float*)d_in[12];
    float* out = (float*)d_out;

    float *bufQ, *buf1, *buf2, *buf3, *wInT, *wOutT;
    cudaGetSymbolAddress((void**)&bufQ,  g_qkv);
    cudaGetSymbolAddress((void**)&buf1,  g_buf1);
    cudaGetSymbolAddress((void**)&buf2,  g_buf2);
    cudaGetSymbolAddress((void**)&buf3,  g_buf3);
    cudaGetSymbolAddress((void**)&wInT,  g_wInT);
    cudaGetSymbolAddress((void**)&wOutT, g_wOutT);

    k_init_A<<<1, 1>>>();
    k_transpose<<<(E3 * HID + 255) / 256, 256>>>(inW, wInT, E3, HID);
    k_transpose<<<(HID * HID + 255) / 256, 256>>>(outW, wOutT, HID, HID);

    dim3 gH(HID / 64, MROWS / 128);   // N=256 GEMMs
    dim3 gQ(E3 / 64,  MROWS / 128);   // N=768 GEMM

    // gcn1: T1 = x @ W1; h1 = relu(A@T1 + b1)
    k_sgemm<false><<<gH, 256>>>(x, W1, nullptr, buf1, MROWS, HID, FIN);
    k_mix<true><<<B_SZ, 256>>>(buf1, b1, buf2);

    // gcn2: T2 = h1 @ W2; h2 = relu(A@T2 + b2)
    k_sgemm<false><<<gH, 256>>>(buf2, W2, nullptr, buf1, MROWS, HID, HID);
    k_mix<true><<<B_SZ, 256>>>(buf1, b2, buf3);          // buf3 = h2 (kept for residual)

    // qkv = h2 @ in_proj_w^T + in_proj_b
    k_sgemm<true><<<gQ, 256>>>(buf3, wInT, inB, bufQ, MROWS, E3, HID);

    // attention -> buf1
    k_attn<<<B_SZ, 128>>>(bufQ, buf1);

    // att = o @ out_proj_w^T + out_proj_b -> buf2
    k_sgemm<true><<<gH, 256>>>(buf1, wOutT, outB, buf2, MROWS, HID, HID);

    // hn = LN(h2 + att) -> buf1
    k_ln<<<MROWS / 8, 256>>>(buf3, buf2, lng, lnb, buf1);

    // T3 = hn @ W3 -> buf2
    k_sgemm<false><<<gH, 256>>>(buf1, W3, nullptr, buf2, MROWS, HID, HID);

    // h3 = A@T3 + b3, pooling, concat -> out
    k_final<<<B_SZ, 256>>>(buf2, b3, out);
}

// round 3
// speedup vs baseline: 1.8397x; 1.8397x over previous
#include <cuda_runtime.h>
#include <cuda_bf16.h>
#include <cstdint>
#include <math.h>

#define B_SZ   8192
#define LEADS  12
#define FIN    512
#define HID    256
#define E3     768
#define MROWS  (B_SZ * LEADS)   // 98304

// ---------------- static scratch (no allocation allowed) ----------------
__device__ float g_A[LEADS * LEADS];
__device__ float g_qkv[(size_t)MROWS * E3];
__device__ float g_buf1[(size_t)MROWS * HID];
__device__ float g_buf2[(size_t)MROWS * HID];
__device__ float g_buf3[(size_t)MROWS * HID];

// split-bf16 weights, stored [N, K] K-major
__device__ __nv_bfloat16 g_W1h[HID * FIN], g_W1l[HID * FIN];
__device__ __nv_bfloat16 g_W2h[HID * HID], g_W2l[HID * HID];
__device__ __nv_bfloat16 g_W3h[HID * HID], g_W3l[HID * HID];
__device__ __nv_bfloat16 g_Ih[E3 * HID],  g_Il[E3 * HID];
__device__ __nv_bfloat16 g_Oh[HID * HID], g_Ol[HID * HID];

// ---------------- helpers ----------------
__device__ __forceinline__ uint32_t smem_u32(const void* p) {
    uint32_t a;
    asm("{ .reg .u64 t; cvta.to.shared.u64 t, %1; cvt.u32.u64 %0, t; }" : "=r"(a) : "l"(p));
    return a;
}
__device__ __forceinline__ void ldsm4(uint32_t& r0, uint32_t& r1, uint32_t& r2, uint32_t& r3,
                                      uint32_t a) {
    asm volatile("ldmatrix.sync.aligned.m8n8.x4.shared.b16 {%0,%1,%2,%3}, [%4];"
                 : "=r"(r0), "=r"(r1), "=r"(r2), "=r"(r3) : "r"(a));
}
__device__ __forceinline__ void mma16816(float* c, const uint32_t* a, const uint32_t* b) {
    asm volatile("mma.sync.aligned.m16n8k16.row.col.f32.bf16.bf16.f32 "
                 "{%0,%1,%2,%3}, {%4,%5,%6,%7}, {%8,%9}, {%0,%1,%2,%3};"
                 : "+f"(c[0]), "+f"(c[1]), "+f"(c[2]), "+f"(c[3])
                 : "r"(a[0]), "r"(a[1]), "r"(a[2]), "r"(a[3]), "r"(b[0]), "r"(b[1]));
}

// ---------------- A_norm init ----------------
__global__ void k_init_A() {
    if (threadIdx.x != 0 || blockIdx.x != 0) return;
    const int ci[18] = {0,0,1,0,1,2,0,1,1,2,6,7,8,9,10,0,1,2};
    const int cj[18] = {1,2,2,3,3,3,4,4,5,5,7,8,9,10,11,6,9,11};
    float A[12][12];
    for (int i = 0; i < 12; i++)
        for (int j = 0; j < 12; j++) A[i][j] = (i == j) ? 1.0f : 0.0f;
    for (int e = 0; e < 18; e++) { A[ci[e]][cj[e]] = 1.0f; A[cj[e]][ci[e]] = 1.0f; }
    float dinv[12];
    for (int i = 0; i < 12; i++) {
        float s = 0.0f;
        for (int j = 0; j < 12; j++) s += A[i][j];
        dinv[i] = 1.0f / sqrtf(s);
    }
    for (int i = 0; i < 12; i++)
        for (int j = 0; j < 12; j++) g_A[i * 12 + j] = dinv[i] * A[i][j] * dinv[j];
}

// ---------------- weight split prep ----------------
__global__ void k_split_t(const float* __restrict__ src, __nv_bfloat16* __restrict__ h,
                          __nv_bfloat16* __restrict__ l, int K, int N) {
    int idx = blockIdx.x * blockDim.x + threadIdx.x;
    if (idx >= K * N) return;
    int k = idx / N, n = idx % N;
    float v = src[idx];
    __nv_bfloat16 hi = __float2bfloat16(v);
    h[(size_t)n * K + k] = hi;
    l[(size_t)n * K + k] = __float2bfloat16(v - __bfloat162float(hi));
}
__global__ void k_split(const float* __restrict__ src, __nv_bfloat16* __restrict__ h,
                        __nv_bfloat16* __restrict__ l, int count) {
    int idx = blockIdx.x * blockDim.x + threadIdx.x;
    if (idx >= count) return;
    float v = src[idx];
    __nv_bfloat16 hi = __float2bfloat16(v);
    h[idx] = hi;
    l[idx] = __float2bfloat16(v - __bfloat162float(hi));
}

// ---------------- mma.sync split-bf16 GEMM ----------------
// C[M,N] = A[M,K](fp32, split on the fly) @ B^T (+bias), B as [N,K] bf16 hi/lo.
// Block tile 128x128, 512 threads (16 warps 4x4), warp tile 32x32, BK=32.
// smem stage (bf16 units, rows padded to 40): Ah[128][40] @0, Al @5120,
// Bh @10240, Bl @15360; stage stride 20480 (40960 B); 2 stages.
#define SROW 40
#define STAGE_ELEMS 20480
#define SMEM_BYTES  (2 * STAGE_ELEMS * 2)

template <bool BIAS>
__global__ __launch_bounds__(512, 1) void k_hgemm(
    const float* __restrict__ A,
    const __nv_bfloat16* __restrict__ Bh,
    const __nv_bfloat16* __restrict__ Bl,
    const float* __restrict__ bias,
    float* __restrict__ C,
    int K, int N)
{
    extern __shared__ __nv_bfloat16 sm[];
    const int tid  = threadIdx.x;
    const int lane = tid & 31;
    const int w    = tid >> 5;
    const int wm   = w >> 2;        // 0..3
    const int wn   = w & 3;         // 0..3
    const int row0 = blockIdx.y * 128;
    const int col0 = blockIdx.x * 128;
    const int NC   = K >> 5;

    const uint32_t sbase = smem_u32(sm);

    // ldmatrix lane-address components
    const int arow  = (lane & 7) | (((lane >> 3) & 1) << 3);  // 0..15
    const int akblk = (lane >> 4) & 1;
    const int bwhich = lane >> 3;          // 0..3
    const int bn     = lane & 7;
    const int bkblk  = bwhich & 1;
    const int bntoff = bwhich >> 1;

    float c[2][4][4];
#pragma unroll
    for (int i = 0; i < 2; i++)
#pragma unroll
        for (int j = 0; j < 4; j++)
#pragma unroll
            for (int q = 0; q < 4; q++) c[i][j][q] = 0.0f;

    // per-thread load coordinates (2 iters each)
    // A: float4 units: e = tid + 512*i; r=e>>3, q=e&7
    // B: uint2 (4 bf16) units: same mapping
    const float*         Abase  = A  + (size_t)row0 * K;
    const __nv_bfloat16* Bhbase = Bh + (size_t)col0 * K;
    const __nv_bfloat16* Blbase = Bl + (size_t)col0 * K;

    float4 pa[2];
    uint2  pbh[2], pbl[2];

    auto ldg_chunk = [&](int cchunk) {
#pragma unroll
        for (int i = 0; i < 2; i++) {
            int e = tid + 512 * i;
            int r = e >> 3, q = e & 7;
            pa[i]  = *(const float4*)(Abase  + (size_t)r * K + cchunk * 32 + q * 4);
            pbh[i] = *(const uint2*)(Bhbase + (size_t)r * K + cchunk * 32 + q * 4);
            pbl[i] = *(const uint2*)(Blbase + (size_t)r * K + cchunk * 32 + q * 4);
        }
    };
    auto sts_chunk = [&](int s) {
        __nv_bfloat16* st = sm + s * STAGE_ELEMS;
#pragma unroll
        for (int i = 0; i < 2; i++) {
            int e = tid + 512 * i;
            int r = e >> 3, q = e & 7;
            float v[4] = {pa[i].x, pa[i].y, pa[i].z, pa[i].w};
            __nv_bfloat16 h[4], l[4];
#pragma unroll
            for (int t = 0; t < 4; t++) {
                h[t] = __float2bfloat16(v[t]);
                l[t] = __float2bfloat16(v[t] - __bfloat162float(h[t]));
            }
            int off = r * SROW + q * 4;
            *(__nv_bfloat162*)(st + off)            = __halves2bfloat162(h[0], h[1]);
            *(__nv_bfloat162*)(st + off + 2)        = __halves2bfloat162(h[2], h[3]);
            *(__nv_bfloat162*)(st + 5120 + off)     = __halves2bfloat162(l[0], l[1]);
            *(__nv_bfloat162*)(st + 5120 + off + 2) = __halves2bfloat162(l[2], l[3]);
            *(uint2*)(st + 10240 + off) = pbh[i];
            *(uint2*)(st + 15360 + off) = pbl[i];
        }
    };

    auto compute = [&](int s) {
        uint32_t so = sbase + s * (STAGE_ELEMS * 2);
#pragma unroll
        for (int ks = 0; ks < 2; ks++) {
            uint32_t ah[2][4], al[2][4];
#pragma unroll
            for (int mt = 0; mt < 2; mt++) {
                uint32_t aoff = so + ((wm * 32 + mt * 16 + arow) * SROW + ks * 16 + akblk * 8) * 2;
                ldsm4(ah[mt][0], ah[mt][1], ah[mt][2], ah[mt][3], aoff);
                ldsm4(al[mt][0], al[mt][1], al[mt][2], al[mt][3], aoff + 5120 * 2);
            }
            uint32_t bh[2][4], bl[2][4];
#pragma unroll
            for (int p = 0; p < 2; p++) {
                int nt = p * 2 + bntoff;
                uint32_t boff = so + (10240 + (wn * 32 + nt * 8 + bn) * SROW + ks * 16 + bkblk * 8) * 2;
                ldsm4(bh[p][0], bh[p][1], bh[p][2], bh[p][3], boff);
                ldsm4(bl[p][0], bl[p][1], bl[p][2], bl[p][3], boff + 5120 * 2);
            }
#pragma unroll
            for (int mt = 0; mt < 2; mt++)
#pragma unroll
                for (int p = 0; p < 2; p++)
#pragma unroll
                    for (int h = 0; h < 2; h++) {
                        int nt = p * 2 + h;
                        mma16816(c[mt][nt], ah[mt], &bh[p][h * 2]);  // hi*hi
                        mma16816(c[mt][nt], ah[mt], &bl[p][h * 2]);  // hi*lo
                        mma16816(c[mt][nt], al[mt], &bh[p][h * 2]);  // lo*hi
                    }
        }
    };

    ldg_chunk(0);
    sts_chunk(0);
    __syncthreads();

    for (int cc = 0; cc < NC; cc++) {
        if (cc + 1 < NC) ldg_chunk(cc + 1);
        compute(cc & 1);
        if (cc + 1 < NC) sts_chunk((cc + 1) & 1);
        __syncthreads();
    }

    // epilogue
#pragma unroll
    for (int mt = 0; mt < 2; mt++) {
        int row = row0 + wm * 32 + mt * 16 + (lane >> 2);
#pragma unroll
        for (int nt = 0; nt < 4; nt++) {
            int col = col0 + wn * 32 + nt * 8 + (lane & 3) * 2;
            float b0 = 0.0f, b1 = 0.0f;
            if (BIAS) { b0 = bias[col]; b1 = bias[col + 1]; }
            float2 o0 = {c[mt][nt][0] + b0, c[mt][nt][1] + b1};
            float2 o1 = {c[mt][nt][2] + b0, c[mt][nt][3] + b1};
            *(float2*)(C + (size_t)row * N + col)       = o0;
            *(float2*)(C + (size_t)(row + 8) * N + col) = o1;
        }
    }
}

// ---------------- lead-mix ----------------
template <bool RELU>
__global__ __launch_bounds__(256) void k_mix(
    const float* __restrict__ T, const float* __restrict__ bias,
    float* __restrict__ out)
{
    int b = blockIdx.x, f = threadIdx.x;
    float t[LEADS];
#pragma unroll
    for (int j = 0; j < LEADS; j++)
        t[j] = T[((size_t)b * LEADS + j) * HID + f];
    float bv = bias[f];
#pragma unroll
    for (int i = 0; i < LEADS; i++) {
        float acc = bv;
#pragma unroll
        for (int j = 0; j < LEADS; j++) acc += g_A[i * 12 + j] * t[j];
        if (RELU) acc = fmaxf(acc, 0.0f);
        out[((size_t)b * LEADS + i) * HID + f] = acc;
    }
}

// ---------------- attention ----------------
__global__ __launch_bounds__(128) void k_attn(const float* __restrict__ qkv,
                                              float* __restrict__ o)
{
    __shared__ float sq[4][12 * 64];
    __shared__ float sk[4][12 * 64];
    __shared__ float sv[4][12 * 64];
    __shared__ float ss[4][12][12];

    int b    = blockIdx.x;
    int w    = threadIdx.x >> 5;
    int lane = threadIdx.x & 31;
    const float* base = qkv + (size_t)b * LEADS * E3;

    for (int idx = lane; idx < 768; idx += 32) {
        int s = idx >> 6, d = idx & 63;
        sq[w][idx] = base[s * E3 +       w * 64 + d];
        sk[w][idx] = base[s * E3 + 256 + w * 64 + d];
        sv[w][idx] = base[s * E3 + 512 + w * 64 + d];
    }
    __syncwarp();

    for (int st = lane; st < 144; st += 32) {
        int s = st / 12, t = st % 12;
        float acc = 0.0f;
#pragma unroll
        for (int d = 0; d < 64; d++) acc += sq[w][s * 64 + d] * sk[w][t * 64 + d];
        ss[w][s][t] = acc * 0.125f;
    }
    __syncwarp();

    if (lane < 12) {
        float mx = -1e30f;
        for (int t = 0; t < 12; t++) mx = fmaxf(mx, ss[w][lane][t]);
        float e[12], sum = 0.0f;
        for (int t = 0; t < 12; t++) { e[t] = expf(ss[w][lane][t] - mx); sum += e[t]; }
        float inv = 1.0f / sum;
        for (int t = 0; t < 12; t++) ss[w][lane][t] = e[t] * inv;
    }
    __syncwarp();

    for (int idx = lane; idx < 768; idx += 32) {
        int s = idx >> 6, d = idx & 63;
        float acc = 0.0f;
#pragma unroll
        for (int t = 0; t < 12; t++) acc += ss[w][s][t] * sv[w][t * 64 + d];
        o[((size_t)b * LEADS + s) * HID + w * 64 + d] = acc;
    }
}

// ---------------- residual + LayerNorm ----------------
__global__ __launch_bounds__(256) void k_ln(
    const float* __restrict__ h, const float* __restrict__ a,
    const float* __restrict__ g, const float* __restrict__ bta,
    float* __restrict__ out)
{
    int row  = blockIdx.x * 8 + (threadIdx.x >> 5);
    int lane = threadIdx.x & 31;
    const float* hp = h + (size_t)row * HID;
    const float* ap = a + (size_t)row * HID;

    float v[8];
    float sum = 0.0f;
#pragma unroll
    for (int j = 0; j < 8; j++) {
        int cidx = lane + 32 * j;
        v[j] = hp[cidx] + ap[cidx];
        sum += v[j];
    }
#pragma unroll
    for (int off = 16; off; off >>= 1) sum += __shfl_xor_sync(0xFFFFFFFFu, sum, off);
    float mu = sum * (1.0f / 256.0f);

    float vs = 0.0f;
#pragma unroll
    for (int j = 0; j < 8; j++) { float d = v[j] - mu; vs += d * d; }
#pragma unroll
    for (int off = 16; off; off >>= 1) vs += __shfl_xor_sync(0xFFFFFFFFu, vs, off);
    float rs = rsqrtf(vs * (1.0f / 256.0f) + 1e-5f);

#pragma unroll
    for (int j = 0; j < 8; j++) {
        int cidx = lane + 32 * j;
        out[(size_t)row * HID + cidx] = (v[j] - mu) * rs * g[cidx] + bta[cidx];
    }
}

// ---------------- final: gcn3 mix + pooling ----------------
__global__ __launch_bounds__(256) void k_final(
    const float* __restrict__ T3, const float* __restrict__ b3,
    float* __restrict__ out)
{
    __shared__ float red[12][8];
    __shared__ float sw[12];
    int b = blockIdx.x, f = threadIdx.x;
    int lane = f & 31, wid = f >> 5;

    float t[LEADS];
#pragma unroll
    for (int j = 0; j < LEADS; j++)
        t[j] = T3[((size_t)b * LEADS + j) * HID + f];

    float bias = b3[f];
    float h3[LEADS];
#pragma unroll
    for (int i = 0; i < LEADS; i++) {
        float acc = bias;
#pragma unroll
        for (int j = 0; j < LEADS; j++) acc += g_A[i * 12 + j] * t[j];
        h3[i] = acc;
    }

#pragma unroll
    for (int i = 0; i < LEADS; i++) {
        float s = h3[i];
#pragma unroll
        for (int off = 16; off; off >>= 1) s += __shfl_xor_sync(0xFFFFFFFFu, s, off);
        if (lane == 0) red[i][wid] = s;
    }
    __syncthreads();
    if (f < 12) {
        float s = 0.0f;
        for (int w = 0; w < 8; w++) s += red[f][w];
        sw[f] = s * (1.0f / 256.0f);
    }
    __syncthreads();
    if (f == 0) {
        float mx = -1e30f;
        for (int i = 0; i < 12; i++) mx = fmaxf(mx, sw[i]);
        float e[12], sum = 0.0f;
        for (int i = 0; i < 12; i++) { e[i] = expf(sw[i] - mx); sum += e[i]; }
        float inv = 1.0f / sum;
        for (int i = 0; i < 12; i++) sw[i] = e[i] * inv;
    }
    __syncthreads();

    float ws = 0.0f, mx = -1e30f;
#pragma unroll
    for (int i = 0; i < LEADS; i++) {
        ws += h3[i] * sw[i];
        mx = fmaxf(mx, h3[i]);
    }
    out[(size_t)b * 512 + f]       = ws;
    out[(size_t)b * 512 + 256 + f] = mx;
}

// ---------------- launcher ----------------
extern "C" void kernel_launch(void* const* d_in, const int* in_sizes, int n_in,
                              void* d_out, int out_size)
{
    const float* x    = (const float*)d_in[0];
    const float* W1   = (const float*)d_in[1];
    const float* b1   = (const float*)d_in[2];
    const float* W2   = (const float*)d_in[3];
    const float* b2   = (const float*)d_in[4];
    const float* W3   = (const float*)d_in[5];
    const float* b3   = (const float*)d_in[6];
    const float* inW  = (const float*)d_in[7];
    const float* inB  = (const float*)d_in[8];
    const float* outW = (const float*)d_in[9];
    const float* outB = (const float*)d_in[10];
    const float* lng  = (const float*)d_in[11];
    const float* lnb  = (const float*)d_in[12];
    float* out = (float*)d_out;

    float *bufQ, *buf1, *buf2, *buf3;
    cudaGetSymbolAddress((void**)&bufQ, g_qkv);
    cudaGetSymbolAddress((void**)&buf1, g_buf1);
    cudaGetSymbolAddress((void**)&buf2, g_buf2);
    cudaGetSymbolAddress((void**)&buf3, g_buf3);

    __nv_bfloat16 *w1h, *w1l, *w2h, *w2l, *w3h, *w3l, *ih, *il, *oh, *ol;
    cudaGetSymbolAddress((void**)&w1h, g_W1h); cudaGetSymbolAddress((void**)&w1l, g_W1l);
    cudaGetSymbolAddress((void**)&w2h, g_W2h); cudaGetSymbolAddress((void**)&w2l, g_W2l);
    cudaGetSymbolAddress((void**)&w3h, g_W3h); cudaGetSymbolAddress((void**)&w3l, g_W3l);
    cudaGetSymbolAddress((void**)&ih,  g_Ih);  cudaGetSymbolAddress((void**)&il,  g_Il);
    cudaGetSymbolAddress((void**)&oh,  g_Oh);  cudaGetSymbolAddress((void**)&ol,  g_Ol);

    cudaFuncSetAttribute(k_hgemm<false>, cudaFuncAttributeMaxDynamicSharedMemorySize, SMEM_BYTES);
    cudaFuncSetAttribute(k_hgemm<true>,  cudaFuncAttributeMaxDynamicSharedMemorySize, SMEM_BYTES);

    k_init_A<<<1, 1>>>();
    k_split_t<<<(FIN * HID + 255) / 256, 256>>>(W1, w1h, w1l, FIN, HID);
    k_split_t<<<(HID * HID + 255) / 256, 256>>>(W2, w2h, w2l, HID, HID);
    k_split_t<<<(HID * HID + 255) / 256, 256>>>(W3, w3h, w3l, HID, HID);
    k_split<<<(E3 * HID + 255) / 256, 256>>>(inW, ih, il, E3 * HID);
    k_split<<<(HID * HID + 255) / 256, 256>>>(outW, oh, ol, HID * HID);

    dim3 gH(2, MROWS / 128);   // N=256
    dim3 gQ(6, MROWS / 128);   // N=768

    // gcn1: T1 = x @ W1; h1 = relu(A@T1 + b1)
    k_hgemm<false><<<gH, 512, SMEM_BYTES>>>(x, w1h, w1l, nullptr, buf1, FIN, HID);
    k_mix<true><<<B_SZ, 256>>>(buf1, b1, buf2);

    // gcn2
    k_hgemm<false><<<gH, 512, SMEM_BYTES>>>(buf2, w2h, w2l, nullptr, buf1, HID, HID);
    k_mix<true><<<B_SZ, 256>>>(buf1, b2, buf3);     // buf3 = h2 (residual)

    // qkv = h2 @ in_proj_w^T + in_proj_b
    k_hgemm<true><<<gQ, 512, SMEM_BYTES>>>(buf3, ih, il, inB, bufQ, HID, E3);

    // attention -> buf1
    k_attn<<<B_SZ, 128>>>(bufQ, buf1);

    // att = o @ out_proj_w^T + out_proj_b -> buf2
    k_hgemm<true><<<gH, 512, SMEM_BYTES>>>(buf1, oh, ol, outB, buf2, HID, HID);

    // hn = LN(h2 + att) -> buf1
    k_ln<<<MROWS / 8, 256>>>(buf3, buf2, lng, lnb, buf1);

    // T3 = hn @ W3 -> buf2
    k_hgemm<false><<<gH, 512, SMEM_BYTES>>>(buf1, w3h, w3l, nullptr, buf2, HID, HID);

    // pooling
    k_final<<<B_SZ, 256>>>(buf2, b3, out);
}

// round 4
// speedup vs baseline: 2.1548x; 1.1713x over previous
#include <cuda_runtime.h>
#include <cuda_fp16.h>
#include <cstdint>
#include <math.h>

#define B_SZ   8192
#define LEADS  12
#define FIN    512
#define HID    256
#define E3     768
#define MROWS  (B_SZ * LEADS)   // 98304

// ---------------- static scratch (no allocation allowed) ----------------
__device__ float g_A[LEADS * LEADS];
__device__ float g_qkv[(size_t)MROWS * E3];
__device__ float g_buf1[(size_t)MROWS * HID];
__device__ float g_buf2[(size_t)MROWS * HID];
__device__ float g_buf3[(size_t)MROWS * HID];

// split-fp16 weights, stored [N, K] K-major (hi + lo)
__device__ __half g_W1h[HID * FIN], g_W1l[HID * FIN];
__device__ __half g_W2h[HID * HID], g_W2l[HID * HID];
__device__ __half g_W3h[HID * HID], g_W3l[HID * HID];
__device__ __half g_Ih[E3 * HID],  g_Il[E3 * HID];
__device__ __half g_Oh[HID * HID], g_Ol[HID * HID];

// ---------------- helpers ----------------
__device__ __forceinline__ uint32_t smem_u32(const void* p) {
    uint32_t a;
    asm("{ .reg .u64 t; cvta.to.shared.u64 t, %1; cvt.u32.u64 %0, t; }" : "=r"(a) : "l"(p));
    return a;
}
__device__ __forceinline__ void ldsm4(uint32_t& r0, uint32_t& r1, uint32_t& r2, uint32_t& r3,
                                      uint32_t a) {
    asm volatile("ldmatrix.sync.aligned.m8n8.x4.shared.b16 {%0,%1,%2,%3}, [%4];"
                 : "=r"(r0), "=r"(r1), "=r"(r2), "=r"(r3) : "r"(a));
}
__device__ __forceinline__ void mma16816(float* c, const uint32_t* a, const uint32_t* b) {
    asm volatile("mma.sync.aligned.m16n8k16.row.col.f32.f16.f16.f32 "
                 "{%0,%1,%2,%3}, {%4,%5,%6,%7}, {%8,%9}, {%0,%1,%2,%3};"
                 : "+f"(c[0]), "+f"(c[1]), "+f"(c[2]), "+f"(c[3])
                 : "r"(a[0]), "r"(a[1]), "r"(a[2]), "r"(a[3]), "r"(b[0]), "r"(b[1]));
}

// ---------------- A_norm init ----------------
__global__ void k_init_A() {
    if (threadIdx.x != 0 || blockIdx.x != 0) return;
    const int ci[18] = {0,0,1,0,1,2,0,1,1,2,6,7,8,9,10,0,1,2};
    const int cj[18] = {1,2,2,3,3,3,4,4,5,5,7,8,9,10,11,6,9,11};
    float A[12][12];
    for (int i = 0; i < 12; i++)
        for (int j = 0; j < 12; j++) A[i][j] = (i == j) ? 1.0f : 0.0f;
    for (int e = 0; e < 18; e++) { A[ci[e]][cj[e]] = 1.0f; A[cj[e]][ci[e]] = 1.0f; }
    float dinv[12];
    for (int i = 0; i < 12; i++) {
        float s = 0.0f;
        for (int j = 0; j < 12; j++) s += A[i][j];
        dinv[i] = 1.0f / sqrtf(s);
    }
    for (int i = 0; i < 12; i++)
        for (int j = 0; j < 12; j++) g_A[i * 12 + j] = dinv[i] * A[i][j] * dinv[j];
}

// ---------------- weight split prep ----------------
// src [K,N] fp32 -> dst [N,K] fp16 hi/lo
__global__ void k_split_t(const float* __restrict__ src, __half* __restrict__ h,
                          __half* __restrict__ l, int K, int N) {
    int idx = blockIdx.x * blockDim.x + threadIdx.x;
    if (idx >= K * N) return;
    int k = idx / N, n = idx % N;
    float v = src[idx];
    __half hi = __float2half_rn(v);
    h[(size_t)n * K + k] = hi;
    l[(size_t)n * K + k] = __float2half_rn(v - __half2float(hi));
}
// src already [N,K] fp32 -> fp16 hi/lo
__global__ void k_split(const float* __restrict__ src, __half* __restrict__ h,
                        __half* __restrict__ l, int count) {
    int idx = blockIdx.x * blockDim.x + threadIdx.x;
    if (idx >= count) return;
    float v = src[idx];
    __half hi = __float2half_rn(v);
    h[idx] = hi;
    l[idx] = __float2half_rn(v - __half2float(hi));
}

// ---------------- mma.sync split-fp16 GEMM (2-term) ----------------
// C[M,N] = A[M,K](fp32 -> fp16 on the fly) @ B^T (+bias), B as [N,K] fp16 hi/lo.
// out = A_f16 @ (B_h + B_l) = A_f16 @ B exactly; error = fp16 quantization of A.
// Block tile 128x128, 512 threads (16 warps 4x4), warp tile 32x32, BK=32.
// smem stage (half units, rows padded to 40): A[128][40] @0, Bh @5120, Bl @10240;
// stage stride 15360 halves (30720 B); 2 stages.
#define SROW 40
#define STAGE_ELEMS 15360
#define SMEM_BYTES  (2 * STAGE_ELEMS * 2)

template <bool BIAS>
__global__ __launch_bounds__(512, 1) void k_hgemm(
    const float* __restrict__ A,
    const __half* __restrict__ Bh,
    const __half* __restrict__ Bl,
    const float* __restrict__ bias,
    float* __restrict__ C,
    int K, int N)
{
    extern __shared__ __half sm[];
    const int tid  = threadIdx.x;
    const int lane = tid & 31;
    const int w    = tid >> 5;
    const int wm   = w >> 2;        // 0..3
    const int wn   = w & 3;         // 0..3
    const int row0 = blockIdx.y * 128;
    const int col0 = blockIdx.x * 128;
    const int NC   = K >> 5;

    const uint32_t sbase = smem_u32(sm);

    // ldmatrix lane-address components
    const int arow  = (lane & 7) | (((lane >> 3) & 1) << 3);  // 0..15
    const int akblk = (lane >> 4) & 1;
    const int bwhich = lane >> 3;          // 0..3
    const int bn     = lane & 7;
    const int bkblk  = bwhich & 1;
    const int bntoff = bwhich >> 1;

    float c[2][4][4];
#pragma unroll
    for (int i = 0; i < 2; i++)
#pragma unroll
        for (int j = 0; j < 4; j++)
#pragma unroll
            for (int q = 0; q < 4; q++) c[i][j][q] = 0.0f;

    const float*  Abase  = A  + (size_t)row0 * K;
    const __half* Bhbase = Bh + (size_t)col0 * K;
    const __half* Blbase = Bl + (size_t)col0 * K;

    float4 pa[2];
    uint2  pbh[2], pbl[2];

    auto ldg_chunk = [&](int cchunk) {
#pragma unroll
        for (int i = 0; i < 2; i++) {
            int e = tid + 512 * i;
            int r = e >> 3, q = e & 7;
            pa[i]  = *(const float4*)(Abase  + (size_t)r * K + cchunk * 32 + q * 4);
            pbh[i] = *(const uint2*)(Bhbase + (size_t)r * K + cchunk * 32 + q * 4);
            pbl[i] = *(const uint2*)(Blbase + (size_t)r * K + cchunk * 32 + q * 4);
        }
    };
    auto sts_chunk = [&](int s) {
        __half* st = sm + s * STAGE_ELEMS;
#pragma unroll
        for (int i = 0; i < 2; i++) {
            int e = tid + 512 * i;
            int r = e >> 3, q = e & 7;
            __half2 h01 = __float22half2_rn(make_float2(pa[i].x, pa[i].y));
            __half2 h23 = __float22half2_rn(make_float2(pa[i].z, pa[i].w));
            int off = r * SROW + q * 4;
            *(__half2*)(st + off)     = h01;
            *(__half2*)(st + off + 2) = h23;
            *(uint2*)(st + 5120  + off) = pbh[i];
            *(uint2*)(st + 10240 + off) = pbl[i];
        }
    };

    auto compute = [&](int s) {
        uint32_t so = sbase + s * (STAGE_ELEMS * 2);
#pragma unroll
        for (int ks = 0; ks < 2; ks++) {
            uint32_t ah[2][4];
#pragma unroll
            for (int mt = 0; mt < 2; mt++) {
                uint32_t aoff = so + ((wm * 32 + mt * 16 + arow) * SROW + ks * 16 + akblk * 8) * 2;
                ldsm4(ah[mt][0], ah[mt][1], ah[mt][2], ah[mt][3], aoff);
            }
            uint32_t bh[2][4], bl[2][4];
#pragma unroll
            for (int p = 0; p < 2; p++) {
                int nt = p * 2 + bntoff;
                uint32_t boff = so + (5120 + (wn * 32 + nt * 8 + bn) * SROW + ks * 16 + bkblk * 8) * 2;
                ldsm4(bh[p][0], bh[p][1], bh[p][2], bh[p][3], boff);
                ldsm4(bl[p][0], bl[p][1], bl[p][2], bl[p][3], boff + 5120 * 2);
            }
#pragma unroll
            for (int mt = 0; mt < 2; mt++)
#pragma unroll
                for (int p = 0; p < 2; p++)
#pragma unroll
                    for (int h = 0; h < 2; h++) {
                        int nt = p * 2 + h;
                        mma16816(c[mt][nt], ah[mt], &bh[p][h * 2]);  // A * B_hi
                        mma16816(c[mt][nt], ah[mt], &bl[p][h * 2]);  // A * B_lo
                    }
        }
    };

    ldg_chunk(0);
    sts_chunk(0);
    __syncthreads();

    for (int cc = 0; cc < NC; cc++) {
        if (cc + 1 < NC) ldg_chunk(cc + 1);
        compute(cc & 1);
        if (cc + 1 < NC) sts_chunk((cc + 1) & 1);
        __syncthreads();
    }

    // epilogue
#pragma unroll
    for (int mt = 0; mt < 2; mt++) {
        int row = row0 + wm * 32 + mt * 16 + (lane >> 2);
#pragma unroll
        for (int nt = 0; nt < 4; nt++) {
            int col = col0 + wn * 32 + nt * 8 + (lane & 3) * 2;
            float b0 = 0.0f, b1 = 0.0f;
            if (BIAS) { b0 = bias[col]; b1 = bias[col + 1]; }
            float2 o0 = {c[mt][nt][0] + b0, c[mt][nt][1] + b1};
            float2 o1 = {c[mt][nt][2] + b0, c[mt][nt][3] + b1};
            *(float2*)(C + (size_t)row * N + col)       = o0;
            *(float2*)(C + (size_t)(row + 8) * N + col) = o1;
        }
    }
}

// ---------------- lead-mix ----------------
template <bool RELU>
__global__ __launch_bounds__(256) void k_mix(
    const float* __restrict__ T, const float* __restrict__ bias,
    float* __restrict__ out)
{
    int b = blockIdx.x, f = threadIdx.x;
    float t[LEADS];
#pragma unroll
    for (int j = 0; j < LEADS; j++)
        t[j] = T[((size_t)b * LEADS + j) * HID + f];
    float bv = bias[f];
#pragma unroll
    for (int i = 0; i < LEADS; i++) {
        float acc = bv;
#pragma unroll
        for (int j = 0; j < LEADS; j++) acc += g_A[i * 12 + j] * t[j];
        if (RELU) acc = fmaxf(acc, 0.0f);
        out[((size_t)b * LEADS + i) * HID + f] = acc;
    }
}

// ---------------- attention ----------------
__global__ __launch_bounds__(128) void k_attn(const float* __restrict__ qkv,
                                              float* __restrict__ o)
{
    __shared__ float sq[4][12 * 64];
    __shared__ float sk[4][12 * 64];
    __shared__ float sv[4][12 * 64];
    __shared__ float ss[4][12][12];

    int b    = blockIdx.x;
    int w    = threadIdx.x >> 5;
    int lane = threadIdx.x & 31;
    const float* base = qkv + (size_t)b * LEADS * E3;

    for (int idx = lane; idx < 768; idx += 32) {
        int s = idx >> 6, d = idx & 63;
        sq[w][idx] = base[s * E3 +       w * 64 + d];
        sk[w][idx] = base[s * E3 + 256 + w * 64 + d];
        sv[w][idx] = base[s * E3 + 512 + w * 64 + d];
    }
    __syncwarp();

    for (int st = lane; st < 144; st += 32) {
        int s = st / 12, t = st % 12;
        float acc = 0.0f;
#pragma unroll
        for (int d = 0; d < 64; d++) acc += sq[w][s * 64 + d] * sk[w][t * 64 + d];
        ss[w][s][t] = acc * 0.125f;
    }
    __syncwarp();

    if (lane < 12) {
        float mx = -1e30f;
        for (int t = 0; t < 12; t++) mx = fmaxf(mx, ss[w][lane][t]);
        float e[12], sum = 0.0f;
        for (int t = 0; t < 12; t++) { e[t] = expf(ss[w][lane][t] - mx); sum += e[t]; }
        float inv = 1.0f / sum;
        for (int t = 0; t < 12; t++) ss[w][lane][t] = e[t] * inv;
    }
    __syncwarp();

    for (int idx = lane; idx < 768; idx += 32) {
        int s = idx >> 6, d = idx & 63;
        float acc = 0.0f;
#pragma unroll
        for (int t = 0; t < 12; t++) acc += ss[w][s][t] * sv[w][t * 64 + d];
        o[((size_t)b * LEADS + s) * HID + w * 64 + d] = acc;
    }
}

// ---------------- residual + LayerNorm ----------------
__global__ __launch_bounds__(256) void k_ln(
    const float* __restrict__ h, const float* __restrict__ a,
    const float* __restrict__ g, const float* __restrict__ bta,
    float* __restrict__ out)
{
    int row  = blockIdx.x * 8 + (threadIdx.x >> 5);
    int lane = threadIdx.x & 31;
    const float* hp = h + (size_t)row * HID;
    const float* ap = a + (size_t)row * HID;

    float v[8];
    float sum = 0.0f;
#pragma unroll
    for (int j = 0; j < 8; j++) {
        int cidx = lane + 32 * j;
        v[j] = hp[cidx] + ap[cidx];
        sum += v[j];
    }
#pragma unroll
    for (int off = 16; off; off >>= 1) sum += __shfl_xor_sync(0xFFFFFFFFu, sum, off);
    float mu = sum * (1.0f / 256.0f);

    float vs = 0.0f;
#pragma unroll
    for (int j = 0; j < 8; j++) { float d = v[j] - mu; vs += d * d; }
#pragma unroll
    for (int off = 16; off; off >>= 1) vs += __shfl_xor_sync(0xFFFFFFFFu, vs, off);
    float rs = rsqrtf(vs * (1.0f / 256.0f) + 1e-5f);

#pragma unroll
    for (int j = 0; j < 8; j++) {
        int cidx = lane + 32 * j;
        out[(size_t)row * HID + cidx] = (v[j] - mu) * rs * g[cidx] + bta[cidx];
    }
}

// ---------------- final: gcn3 mix + pooling ----------------
__global__ __launch_bounds__(256) void k_final(
    const float* __restrict__ T3, const float* __restrict__ b3,
    float* __restrict__ out)
{
    __shared__ float red[12][8];
    __shared__ float sw[12];
    int b = blockIdx.x, f = threadIdx.x;
    int lane = f & 31, wid = f >> 5;

    float t[LEADS];
#pragma unroll
    for (int j = 0; j < LEADS; j++)
        t[j] = T3[((size_t)b * LEADS + j) * HID + f];

    float bias = b3[f];
    float h3[LEADS];
#pragma unroll
    for (int i = 0; i < LEADS; i++) {
        float acc = bias;
#pragma unroll
        for (int j = 0; j < LEADS; j++) acc += g_A[i * 12 + j] * t[j];
        h3[i] = acc;
    }

#pragma unroll
    for (int i = 0; i < LEADS; i++) {
        float s = h3[i];
#pragma unroll
        for (int off = 16; off; off >>= 1) s += __shfl_xor_sync(0xFFFFFFFFu, s, off);
        if (lane == 0) red[i][wid] = s;
    }
    __syncthreads();
    if (f < 12) {
        float s = 0.0f;
        for (int w = 0; w < 8; w++) s += red[f][w];
        sw[f] = s * (1.0f / 256.0f);
    }
    __syncthreads();
    if (f == 0) {
        float mx = -1e30f;
        for (int i = 0; i < 12; i++) mx = fmaxf(mx, sw[i]);
        float e[12], sum = 0.0f;
        for (int i = 0; i < 12; i++) { e[i] = expf(sw[i] - mx); sum += e[i]; }
        float inv = 1.0f / sum;
        for (int i = 0; i < 12; i++) sw[i] = e[i] * inv;
    }
    __syncthreads();

    float ws = 0.0f, mx = -1e30f;
#pragma unroll
    for (int i = 0; i < LEADS; i++) {
        ws += h3[i] * sw[i];
        mx = fmaxf(mx, h3[i]);
    }
    out[(size_t)b * 512 + f]       = ws;
    out[(size_t)b * 512 + 256 + f] = mx;
}

// ---------------- launcher ----------------
extern "C" void kernel_launch(void* const* d_in, const int* in_sizes, int n_in,
                              void* d_out, int out_size)
{
    const float* x    = (const float*)d_in[0];
    const float* W1   = (const float*)d_in[1];
    const float* b1   = (const float*)d_in[2];
    const float* W2   = (const float*)d_in[3];
    const float* b2   = (const float*)d_in[4];
    const float* W3   = (const float*)d_in[5];
    const float* b3   = (const float*)d_in[6];
    const float* inW  = (const float*)d_in[7];
    const float* inB  = (const float*)d_in[8];
    const float* outW = (const float*)d_in[9];
    const float* outB = (const float*)d_in[10];
    const float* lng  = (const float*)d_in[11];
    const float* lnb  = (const float*)d_in[12];
    float* out = (float*)d_out;

    float *bufQ, *buf1, *buf2, *buf3;
    cudaGetSymbolAddress((void**)&bufQ, g_qkv);
    cudaGetSymbolAddress((void**)&buf1, g_buf1);
    cudaGetSymbolAddress((void**)&buf2, g_buf2);
    cudaGetSymbolAddress((void**)&buf3, g_buf3);

    __half *w1h, *w1l, *w2h, *w2l, *w3h, *w3l, *ih, *il, *oh, *ol;
    cudaGetSymbolAddress((void**)&w1h, g_W1h); cudaGetSymbolAddress((void**)&w1l, g_W1l);
    cudaGetSymbolAddress((void**)&w2h, g_W2h); cudaGetSymbolAddress((void**)&w2l, g_W2l);
    cudaGetSymbolAddress((void**)&w3h, g_W3h); cudaGetSymbolAddress((void**)&w3l, g_W3l);
    cudaGetSymbolAddress((void**)&ih,  g_Ih);  cudaGetSymbolAddress((void**)&il,  g_Il);
    cudaGetSymbolAddress((void**)&oh,  g_Oh);  cudaGetSymbolAddress((void**)&ol,  g_Ol);

    cudaFuncSetAttribute(k_hgemm<false>, cudaFuncAttributeMaxDynamicSharedMemorySize, SMEM_BYTES);
    cudaFuncSetAttribute(k_hgemm<true>,  cudaFuncAttributeMaxDynamicSharedMemorySize, SMEM_BYTES);

    k_init_A<<<1, 1>>>();
    k_split_t<<<(FIN * HID + 255) / 256, 256>>>(W1, w1h, w1l, FIN, HID);
    k_split_t<<<(HID * HID + 255) / 256, 256>>>(W2, w2h, w2l, HID, HID);
    k_split_t<<<(HID * HID + 255) / 256, 256>>>(W3, w3h, w3l, HID, HID);
    k_split<<<(E3 * HID + 255) / 256, 256>>>(inW, ih, il, E3 * HID);
    k_split<<<(HID * HID + 255) / 256, 256>>>(outW, oh, ol, HID * HID);

    dim3 gH(2, MROWS / 128);   // N=256
    dim3 gQ(6, MROWS / 128);   // N=768

    // gcn1: T1 = x @ W1; h1 = relu(A@T1 + b1)
    k_hgemm<false><<<gH, 512, SMEM_BYTES>>>(x, w1h, w1l, nullptr, buf1, FIN, HID);
    k_mix<true><<<B_SZ, 256>>>(buf1, b1, buf2);

    // gcn2
    k_hgemm<false><<<gH, 512, SMEM_BYTES>>>(buf2, w2h, w2l, nullptr, buf1, HID, HID);
    k_mix<true><<<B_SZ, 256>>>(buf1, b2, buf3);     // buf3 = h2 (residual)

    // qkv = h2 @ in_proj_w^T + in_proj_b
    k_hgemm<true><<<gQ, 512, SMEM_BYTES>>>(buf3, ih, il, inB, bufQ, HID, E3);

    // attention -> buf1
    k_attn<<<B_SZ, 128>>>(bufQ, buf1);

    // att = o @ out_proj_w^T + out_proj_b -> buf2
    k_hgemm<true><<<gH, 512, SMEM_BYTES>>>(buf1, oh, ol, outB, buf2, HID, HID);

    // hn = LN(h2 + att) -> buf1
    k_ln<<<MROWS / 8, 256>>>(buf3, buf2, lng, lnb, buf1);

    // T3 = hn @ W3 -> buf2
    k_hgemm<false><<<gH, 512, SMEM_BYTES>>>(buf1, w3h, w3l, nullptr, buf2, HID, HID);

    // pooling
    k_final<<<B_SZ, 256>>>(buf2, b3, out);
}

// round 5
// speedup vs baseline: 2.2313x; 1.0355x over previous
#include <cuda_runtime.h>
#include <cuda_fp16.h>
#include <cstdint>
#include <math.h>

#define B_SZ   8192
#define LEADS  12
#define FIN    512
#define HID    256
#define E3     768
#define MROWS  (B_SZ * LEADS)   // 98304

// ---------------- static scratch (no allocation allowed) ----------------
__device__ float g_A[LEADS * LEADS];
__device__ __half g_qkv[(size_t)MROWS * E3];
__device__ __half g_buf1[(size_t)MROWS * HID];
__device__ __half g_buf2[(size_t)MROWS * HID];
__device__ __half g_buf3[(size_t)MROWS * HID];

// split-fp16 weights, stored [N, K] K-major (hi + lo)
__device__ __half g_W1h[HID * FIN], g_W1l[HID * FIN];
__device__ __half g_W2h[HID * HID], g_W2l[HID * HID];
__device__ __half g_W3h[HID * HID], g_W3l[HID * HID];
__device__ __half g_Ih[E3 * HID],  g_Il[E3 * HID];
__device__ __half g_Oh[HID * HID], g_Ol[HID * HID];

// ---------------- helpers ----------------
__device__ __forceinline__ uint32_t smem_u32(const void* p) {
    uint32_t a;
    asm("{ .reg .u64 t; cvta.to.shared.u64 t, %1; cvt.u32.u64 %0, t; }" : "=r"(a) : "l"(p));
    return a;
}
__device__ __forceinline__ void ldsm4(uint32_t& r0, uint32_t& r1, uint32_t& r2, uint32_t& r3,
                                      uint32_t a) {
    asm volatile("ldmatrix.sync.aligned.m8n8.x4.shared.b16 {%0,%1,%2,%3}, [%4];"
                 : "=r"(r0), "=r"(r1), "=r"(r2), "=r"(r3) : "r"(a));
}
__device__ __forceinline__ void mma16816(float* c, const uint32_t* a, const uint32_t* b) {
    asm volatile("mma.sync.aligned.m16n8k16.row.col.f32.f16.f16.f32 "
                 "{%0,%1,%2,%3}, {%4,%5,%6,%7}, {%8,%9}, {%0,%1,%2,%3};"
                 : "+f"(c[0]), "+f"(c[1]), "+f"(c[2]), "+f"(c[3])
                 : "r"(a[0]), "r"(a[1]), "r"(a[2]), "r"(a[3]), "r"(b[0]), "r"(b[1]));
}
__device__ __forceinline__ void cp16(uint32_t d, const void* g) {
    asm volatile("cp.async.ca.shared.global [%0], [%1], 16;" :: "r"(d), "l"(g));
}
#define CP_COMMIT asm volatile("cp.async.commit_group;" ::: "memory")
#define CP_WAIT0  asm volatile("cp.async.wait_group 0;" ::: "memory")

// ---------------- A_norm init ----------------
__global__ void k_init_A() {
    if (threadIdx.x != 0 || blockIdx.x != 0) return;
    const int ci[18] = {0,0,1,0,1,2,0,1,1,2,6,7,8,9,10,0,1,2};
    const int cj[18] = {1,2,2,3,3,3,4,4,5,5,7,8,9,10,11,6,9,11};
    float A[12][12];
    for (int i = 0; i < 12; i++)
        for (int j = 0; j < 12; j++) A[i][j] = (i == j) ? 1.0f : 0.0f;
    for (int e = 0; e < 18; e++) { A[ci[e]][cj[e]] = 1.0f; A[cj[e]][ci[e]] = 1.0f; }
    float dinv[12];
    for (int i = 0; i < 12; i++) {
        float s = 0.0f;
        for (int j = 0; j < 12; j++) s += A[i][j];
        dinv[i] = 1.0f / sqrtf(s);
    }
    for (int i = 0; i < 12; i++)
        for (int j = 0; j < 12; j++) g_A[i * 12 + j] = dinv[i] * A[i][j] * dinv[j];
}

// ---------------- weight split prep ----------------
__global__ void k_split_t(const float* __restrict__ src, __half* __restrict__ h,
                          __half* __restrict__ l, int K, int N) {
    int idx = blockIdx.x * blockDim.x + threadIdx.x;
    if (idx >= K * N) return;
    int k = idx / N, n = idx % N;
    float v = src[idx];
    __half hi = __float2half_rn(v);
    h[(size_t)n * K + k] = hi;
    l[(size_t)n * K + k] = __float2half_rn(v - __half2float(hi));
}
__global__ void k_split(const float* __restrict__ src, __half* __restrict__ h,
                        __half* __restrict__ l, int count) {
    int idx = blockIdx.x * blockDim.x + threadIdx.x;
    if (idx >= count) return;
    float v = src[idx];
    __half hi = __float2half_rn(v);
    h[idx] = hi;
    l[idx] = __float2half_rn(v - __half2float(hi));
}

// ---------------- shared GEMM compute core ----------------
// smem stage (half units, rows padded to SROW=40): A@0, Bh@5120, Bl@10240.
#define SROW 40
#define STAGE_H 15360
#define STAGE_B (STAGE_H * 2)
#define SMEM_BYTES (2 * STAGE_B)

struct GemmCtx {
    int lane, wm, wn;
    int arow, akblk, bn, bkblk, bntoff;
};

__device__ __forceinline__ void gemm_compute(const GemmCtx& g, uint32_t so, float c[2][4][4]) {
#pragma unroll
    for (int ks = 0; ks < 2; ks++) {
        uint32_t ah[2][4];
#pragma unroll
        for (int mt = 0; mt < 2; mt++) {
            uint32_t aoff = so + ((g.wm * 32 + mt * 16 + g.arow) * SROW + ks * 16 + g.akblk * 8) * 2;
            ldsm4(ah[mt][0], ah[mt][1], ah[mt][2], ah[mt][3], aoff);
        }
        uint32_t bh[2][4], bl[2][4];
#pragma unroll
        for (int p = 0; p < 2; p++) {
            int nt = p * 2 + g.bntoff;
            uint32_t boff = so + (5120 + (g.wn * 32 + nt * 8 + g.bn) * SROW + ks * 16 + g.bkblk * 8) * 2;
            ldsm4(bh[p][0], bh[p][1], bh[p][2], bh[p][3], boff);
            ldsm4(bl[p][0], bl[p][1], bl[p][2], bl[p][3], boff + 5120 * 2);
        }
#pragma unroll
        for (int mt = 0; mt < 2; mt++)
#pragma unroll
            for (int p = 0; p < 2; p++)
#pragma unroll
                for (int h = 0; h < 2; h++) {
                    int nt = p * 2 + h;
                    mma16816(c[mt][nt], ah[mt], &bh[p][h * 2]);
                    mma16816(c[mt][nt], ah[mt], &bl[p][h * 2]);
                }
    }
}

__device__ __forceinline__ void gemm_epilogue(const GemmCtx& g, int row0, int col0,
                                              const float* bias, bool use_bias,
                                              __half* C, int N, float c[2][4][4]) {
#pragma unroll
    for (int mt = 0; mt < 2; mt++) {
        int row = row0 + g.wm * 32 + mt * 16 + (g.lane >> 2);
#pragma unroll
        for (int nt = 0; nt < 4; nt++) {
            int col = col0 + g.wn * 32 + nt * 8 + (g.lane & 3) * 2;
            float b0 = 0.0f, b1 = 0.0f;
            if (use_bias) { b0 = bias[col]; b1 = bias[col + 1]; }
            __half2 o0 = __floats2half2_rn(c[mt][nt][0] + b0, c[mt][nt][1] + b1);
            __half2 o1 = __floats2half2_rn(c[mt][nt][2] + b0, c[mt][nt][3] + b1);
            *(__half2*)(C + (size_t)row * N + col)       = o0;
            *(__half2*)(C + (size_t)(row + 8) * N + col) = o1;
        }
    }
}

__device__ __forceinline__ GemmCtx make_ctx(int tid) {
    GemmCtx g;
    g.lane = tid & 31;
    int w = tid >> 5;
    g.wm = w >> 2;
    g.wn = w & 3;
    g.arow  = (g.lane & 7) | (((g.lane >> 3) & 1) << 3);
    g.akblk = (g.lane >> 4) & 1;
    int bwhich = g.lane >> 3;
    g.bn     = g.lane & 7;
    g.bkblk  = bwhich & 1;
    g.bntoff = bwhich >> 1;
    return g;
}

// ---------------- GEMM, A fp16 in gmem (pure cp.async) ----------------
template <bool BIAS>
__global__ __launch_bounds__(512, 1) void k_hgemm_f16a(
    const __half* __restrict__ A,
    const __half* __restrict__ Bh,
    const __half* __restrict__ Bl,
    const float* __restrict__ bias,
    __half* __restrict__ C,
    int K, int N)
{
    extern __shared__ __half sm[];
    const int tid  = threadIdx.x;
    const int row0 = blockIdx.y * 128;
    const int col0 = blockIdx.x * 128;
    const int NC   = K >> 5;
    const uint32_t sbase = smem_u32(sm);
    GemmCtx g = make_ctx(tid);

    float c[2][4][4];
#pragma unroll
    for (int i = 0; i < 2; i++)
#pragma unroll
        for (int j = 0; j < 4; j++)
#pragma unroll
            for (int q = 0; q < 4; q++) c[i][j][q] = 0.0f;

    const int r16 = tid >> 2;
    const int q16 = (tid & 3) * 8;
    const __half* Ab  = A  + (size_t)(row0 + r16) * K + q16;
    const __half* Bhb = Bh + (size_t)(col0 + r16) * K + q16;
    const __half* Blb = Bl + (size_t)(col0 + r16) * K + q16;
    const uint32_t doff = (r16 * SROW + q16) * 2;

    auto cpa = [&](int cc, int s) {
        uint32_t st = sbase + s * STAGE_B + doff;
        cp16(st,             Ab  + cc * 32);
        cp16(st + 5120 * 2,  Bhb + cc * 32);
        cp16(st + 10240 * 2, Blb + cc * 32);
    };

    cpa(0, 0); CP_COMMIT; CP_WAIT0;
    __syncthreads();

    for (int cc = 0; cc < NC; cc++) {
        if (cc + 1 < NC) { cpa(cc + 1, (cc + 1) & 1); CP_COMMIT; }
        gemm_compute(g, sbase + (cc & 1) * STAGE_B, c);
        if (cc + 1 < NC) CP_WAIT0;
        __syncthreads();
    }

    gemm_epilogue(g, row0, col0, bias, BIAS, C, N, c);
}

// ---------------- GEMM, A fp32 in gmem (convert path; B via cp.async) ----------------
template <bool BIAS>
__global__ __launch_bounds__(512, 1) void k_hgemm_f32a(
    const float* __restrict__ A,
    const __half* __restrict__ Bh,
    const __half* __restrict__ Bl,
    const float* __restrict__ bias,
    __half* __restrict__ C,
    int K, int N)
{
    extern __shared__ __half sm[];
    const int tid  = threadIdx.x;
    const int row0 = blockIdx.y * 128;
    const int col0 = blockIdx.x * 128;
    const int NC   = K >> 5;
    const uint32_t sbase = smem_u32(sm);
    GemmCtx g = make_ctx(tid);

    float c[2][4][4];
#pragma unroll
    for (int i = 0; i < 2; i++)
#pragma unroll
        for (int j = 0; j < 4; j++)
#pragma unroll
            for (int q = 0; q < 4; q++) c[i][j][q] = 0.0f;

    const float* Abase = A + (size_t)row0 * K;
    const int r16 = tid >> 2;
    const int q16 = (tid & 3) * 8;
    const __half* Bhb = Bh + (size_t)(col0 + r16) * K + q16;
    const __half* Blb = Bl + (size_t)(col0 + r16) * K + q16;
    const uint32_t doff = (r16 * SROW + q16) * 2;

    float4 pa[2];

    auto ldgA = [&](int cc) {
#pragma unroll
        for (int i = 0; i < 2; i++) {
            int e = tid + 512 * i;
            int r = e >> 3, q = e & 7;
            pa[i] = *(const float4*)(Abase + (size_t)r * K + cc * 32 + q * 4);
        }
    };
    auto stsA = [&](int s) {
        __half* st = sm + s * STAGE_H;
#pragma unroll
        for (int i = 0; i < 2; i++) {
            int e = tid + 512 * i;
            int r = e >> 3, q = e & 7;
            int off = r * SROW + q * 4;
            *(__half2*)(st + off)     = __floats2half2_rn(pa[i].x, pa[i].y);
            *(__half2*)(st + off + 2) = __floats2half2_rn(pa[i].z, pa[i].w);
        }
    };
    auto cpaB = [&](int cc, int s) {
        uint32_t st = sbase + s * STAGE_B + doff;
        cp16(st + 5120 * 2,  Bhb + cc * 32);
        cp16(st + 10240 * 2, Blb + cc * 32);
    };

    ldgA(0); cpaB(0, 0); CP_COMMIT; CP_WAIT0; stsA(0);
    __syncthreads();

    for (int cc = 0; cc < NC; cc++) {
        int s2 = (cc + 1) & 1;
        if (cc + 1 < NC) { ldgA(cc + 1); cpaB(cc + 1, s2); CP_COMMIT; }
        gemm_compute(g, sbase + (cc & 1) * STAGE_B, c);
        if (cc + 1 < NC) { CP_WAIT0; stsA(s2); }
        __syncthreads();
    }

    gemm_epilogue(g, row0, col0, bias, BIAS, C, N, c);
}

// ---------------- lead-mix (fp16 in/out, half2) ----------------
template <bool RELU>
__global__ __launch_bounds__(256) void k_mix(
    const __half* __restrict__ T, const float* __restrict__ bias,
    __half* __restrict__ out)
{
    int b  = blockIdx.x * 2 + (threadIdx.x >> 7);
    int f2 = threadIdx.x & 127;
    const __half2* Tb = (const __half2*)(T + (size_t)b * LEADS * HID) + f2;
    float2 t[LEADS];
#pragma unroll
    for (int j = 0; j < LEADS; j++) t[j] = __half22float2(Tb[j * 128]);
    float b0 = bias[f2 * 2], b1 = bias[f2 * 2 + 1];
    __half2* Ob = (__half2*)(out + (size_t)b * LEADS * HID) + f2;
#pragma unroll
    for (int i = 0; i < LEADS; i++) {
        float ax = b0, ay = b1;
#pragma unroll
        for (int j = 0; j < LEADS; j++) {
            float w = g_A[i * 12 + j];
            ax += w * t[j].x; ay += w * t[j].y;
        }
        if (RELU) { ax = fmaxf(ax, 0.0f); ay = fmaxf(ay, 0.0f); }
        Ob[i * 128] = __floats2half2_rn(ax, ay);
    }
}

// ---------------- attention (fp16 qkv in, fp16 out) ----------------
__global__ __launch_bounds__(128) void k_attn(const __half* __restrict__ qkv,
                                              __half* __restrict__ o)
{
    __shared__ float sq[4][12 * 64];
    __shared__ float sk[4][12 * 64];
    __shared__ float sv[4][12 * 64];
    __shared__ float ss[4][12][12];

    int b    = blockIdx.x;
    int w    = threadIdx.x >> 5;
    int lane = threadIdx.x & 31;
    const __half* base = qkv + (size_t)b * LEADS * E3;

    for (int i2 = lane; i2 < 384; i2 += 32) {
        int s = i2 >> 5, d2 = (i2 & 31) * 2;
        float2 vq = __half22float2(*(const __half2*)(base + s * E3 +       w * 64 + d2));
        float2 vk = __half22float2(*(const __half2*)(base + s * E3 + 256 + w * 64 + d2));
        float2 vv = __half22float2(*(const __half2*)(base + s * E3 + 512 + w * 64 + d2));
        sq[w][s * 64 + d2] = vq.x; sq[w][s * 64 + d2 + 1] = vq.y;
        sk[w][s * 64 + d2] = vk.x; sk[w][s * 64 + d2 + 1] = vk.y;
        sv[w][s * 64 + d2] = vv.x; sv[w][s * 64 + d2 + 1] = vv.y;
    }
    __syncwarp();

    for (int st = lane; st < 144; st += 32) {
        int s = st / 12, t = st % 12;
        float acc = 0.0f;
#pragma unroll
        for (int d = 0; d < 64; d++) acc += sq[w][s * 64 + d] * sk[w][t * 64 + d];
        ss[w][s][t] = acc * 0.125f;
    }
    __syncwarp();

    if (lane < 12) {
        float mx = -1e30f;
        for (int t = 0; t < 12; t++) mx = fmaxf(mx, ss[w][lane][t]);
        float e[12], sum = 0.0f;
        for (int t = 0; t < 12; t++) { e[t] = expf(ss[w][lane][t] - mx); sum += e[t]; }
        float inv = 1.0f / sum;
        for (int t = 0; t < 12; t++) ss[w][lane][t] = e[t] * inv;
    }
    __syncwarp();

    for (int i2 = lane; i2 < 384; i2 += 32) {
        int s = i2 >> 5, d2 = (i2 & 31) * 2;
        float a0 = 0.0f, a1 = 0.0f;
#pragma unroll
        for (int t = 0; t < 12; t++) {
            float p = ss[w][s][t];
            a0 += p * sv[w][t * 64 + d2];
            a1 += p * sv[w][t * 64 + d2 + 1];
        }
        *(__half2*)(o + ((size_t)b * LEADS + s) * HID + w * 64 + d2) = __floats2half2_rn(a0, a1);
    }
}

// ---------------- residual + LayerNorm (fp16 in/out) ----------------
__global__ __launch_bounds__(256) void k_ln(
    const __half* __restrict__ h, const __half* __restrict__ a,
    const float* __restrict__ g, const float* __restrict__ bta,
    __half* __restrict__ out)
{
    int row  = blockIdx.x * 8 + (threadIdx.x >> 5);
    int lane = threadIdx.x & 31;
    const __half2* hp = (const __half2*)(h + (size_t)row * HID);
    const __half2* ap = (const __half2*)(a + (size_t)row * HID);

    float v[8];
    float sum = 0.0f;
#pragma unroll
    for (int j = 0; j < 4; j++) {
        int c2 = lane + 32 * j;
        float2 hv = __half22float2(hp[c2]);
        float2 av = __half22float2(ap[c2]);
        v[2 * j]     = hv.x + av.x;
        v[2 * j + 1] = hv.y + av.y;
        sum += v[2 * j] + v[2 * j + 1];
    }
#pragma unroll
    for (int off = 16; off; off >>= 1) sum += __shfl_xor_sync(0xFFFFFFFFu, sum, off);
    float mu = sum * (1.0f / 256.0f);

    float vs = 0.0f;
#pragma unroll
    for (int j = 0; j < 8; j++) { float d = v[j] - mu; vs += d * d; }
#pragma unroll
    for (int off = 16; off; off >>= 1) vs += __shfl_xor_sync(0xFFFFFFFFu, vs, off);
    float rs = rsqrtf(vs * (1.0f / 256.0f) + 1e-5f);

    __half2* op = (__half2*)(out + (size_t)row * HID);
#pragma unroll
    for (int j = 0; j < 4; j++) {
        int c2 = lane + 32 * j;
        float o0 = (v[2 * j]     - mu) * rs * g[c2 * 2]     + bta[c2 * 2];
        float o1 = (v[2 * j + 1] - mu) * rs * g[c2 * 2 + 1] + bta[c2 * 2 + 1];
        op[c2] = __floats2half2_rn(o0, o1);
    }
}

// ---------------- final: gcn3 mix + pooling (fp16 in, fp32 out) ----------------
__global__ __launch_bounds__(256) void k_final(
    const __half* __restrict__ T3, const float* __restrict__ b3,
    float* __restrict__ out)
{
    __shared__ float red[12][8];
    __shared__ float sw[12];
    int b = blockIdx.x, f = threadIdx.x;
    int lane = f & 31, wid = f >> 5;

    float t[LEADS];
#pragma unroll
    for (int j = 0; j < LEADS; j++)
        t[j] = __half2float(T3[((size_t)b * LEADS + j) * HID + f]);

    float bias = b3[f];
    float h3[LEADS];
#pragma unroll
    for (int i = 0; i < LEADS; i++) {
        float acc = bias;
#pragma unroll
        for (int j = 0; j < LEADS; j++) acc += g_A[i * 12 + j] * t[j];
        h3[i] = acc;
    }

#pragma unroll
    for (int i = 0; i < LEADS; i++) {
        float s = h3[i];
#pragma unroll
        for (int off = 16; off; off >>= 1) s += __shfl_xor_sync(0xFFFFFFFFu, s, off);
        if (lane == 0) red[i][wid] = s;
    }
    __syncthreads();
    if (f < 12) {
        float s = 0.0f;
        for (int w = 0; w < 8; w++) s += red[f][w];
        sw[f] = s * (1.0f / 256.0f);
    }
    __syncthreads();
    if (f == 0) {
        float mx = -1e30f;
        for (int i = 0; i < 12; i++) mx = fmaxf(mx, sw[i]);
        float e[12], sum = 0.0f;
        for (int i = 0; i < 12; i++) { e[i] = expf(sw[i] - mx); sum += e[i]; }
        float inv = 1.0f / sum;
        for (int i = 0; i < 12; i++) sw[i] = e[i] * inv;
    }
    __syncthreads();

    float ws = 0.0f, mx = -1e30f;
#pragma unroll
    for (int i = 0; i < LEADS; i++) {
        ws += h3[i] * sw[i];
        mx = fmaxf(mx, h3[i]);
    }
    out[(size_t)b * 512 + f]       = ws;
    out[(size_t)b * 512 + 256 + f] = mx;
}

// ---------------- launcher ----------------
extern "C" void kernel_launch(void* const* d_in, const int* in_sizes, int n_in,
                              void* d_out, int out_size)
{
    const float* x    = (const float*)d_in[0];
    const float* W1   = (const float*)d_in[1];
    const float* b1   = (const float*)d_in[2];
    const float* W2   = (const float*)d_in[3];
    const float* b2   = (const float*)d_in[4];
    const float* W3   = (const float*)d_in[5];
    const float* b3   = (const float*)d_in[6];
    const float* inW  = (const float*)d_in[7];
    const float* inB  = (const float*)d_in[8];
    const float* outW = (const float*)d_in[9];
    const float* outB = (const float*)d_in[10];
    const float* lng  = (const float*)d_in[11];
    const float* lnb  = (const float*)d_in[12];
    float* out = (float*)d_out;

    __half *bufQ, *buf1, *buf2, *buf3;
    cudaGetSymbolAddress((void**)&bufQ, g_qkv);
    cudaGetSymbolAddress((void**)&buf1, g_buf1);
    cudaGetSymbolAddress((void**)&buf2, g_buf2);
    cudaGetSymbolAddress((void**)&buf3, g_buf3);

    __half *w1h, *w1l, *w2h, *w2l, *w3h, *w3l, *ih, *il, *oh, *ol;
    cudaGetSymbolAddress((void**)&w1h, g_W1h); cudaGetSymbolAddress((void**)&w1l, g_W1l);
    cudaGetSymbolAddress((void**)&w2h, g_W2h); cudaGetSymbolAddress((void**)&w2l, g_W2l);
    cudaGetSymbolAddress((void**)&w3h, g_W3h); cudaGetSymbolAddress((void**)&w3l, g_W3l);
    cudaGetSymbolAddress((void**)&ih,  g_Ih);  cudaGetSymbolAddress((void**)&il,  g_Il);
    cudaGetSymbolAddress((void**)&oh,  g_Oh);  cudaGetSymbolAddress((void**)&ol,  g_Ol);

    cudaFuncSetAttribute(k_hgemm_f32a<false>, cudaFuncAttributeMaxDynamicSharedMemorySize, SMEM_BYTES);
    cudaFuncSetAttribute(k_hgemm_f16a<false>, cudaFuncAttributeMaxDynamicSharedMemorySize, SMEM_BYTES);
    cudaFuncSetAttribute(k_hgemm_f16a<true>,  cudaFuncAttributeMaxDynamicSharedMemorySize, SMEM_BYTES);

    k_init_A<<<1, 1>>>();
    k_split_t<<<(FIN * HID + 255) / 256, 256>>>(W1, w1h, w1l, FIN, HID);
    k_split_t<<<(HID * HID + 255) / 256, 256>>>(W2, w2h, w2l, HID, HID);
    k_split_t<<<(HID * HID + 255) / 256, 256>>>(W3, w3h, w3l, HID, HID);
    k_split<<<(E3 * HID + 255) / 256, 256>>>(inW, ih, il, E3 * HID);
    k_split<<<(HID * HID + 255) / 256, 256>>>(outW, oh, ol, HID * HID);

    dim3 gH(2, MROWS / 128);   // N=256
    dim3 gQ(6, MROWS / 128);   // N=768

    // gcn1: T1 = x @ W1 (fp32 A path); h1 = relu(A@T1 + b1)
    k_hgemm_f32a<false><<<gH, 512, SMEM_BYTES>>>(x, w1h, w1l, nullptr, buf1, FIN, HID);
    k_mix<true><<<B_SZ / 2, 256>>>(buf1, b1, buf2);

    // gcn2
    k_hgemm_f16a<false><<<gH, 512, SMEM_BYTES>>>(buf2, w2h, w2l, nullptr, buf1, HID, HID);
    k_mix<true><<<B_SZ / 2, 256>>>(buf1, b2, buf3);     // buf3 = h2 (residual)

    // qkv = h2 @ in_proj_w^T + in_proj_b
    k_hgemm_f16a<true><<<gQ, 512, SMEM_BYTES>>>(buf3, ih, il, inB, bufQ, HID, E3);

    // attention -> buf1
    k_attn<<<B_SZ, 128>>>(bufQ, buf1);

    // att = o @ out_proj_w^T + out_proj_b -> buf2
    k_hgemm_f16a<true><<<gH, 512, SMEM_BYTES>>>(buf1, oh, ol, outB, buf2, HID, HID);

    // hn = LN(h2 + att) -> buf1
    k_ln<<<MROWS / 8, 256>>>(buf3, buf2, lng, lnb, buf1);

    // T3 = hn @ W3 -> buf2
    k_hgemm_f16a<false><<<gH, 512, SMEM_BYTES>>>(buf1, w3h, w3l, nullptr, buf2, HID, HID);

    // pooling
    k_final<<<B_SZ, 256>>>(buf2, b3, out);
}

// round 6
// speedup vs baseline: 2.7512x; 1.2330x over previous
#include <cuda_runtime.h>
#include <cuda_fp16.h>
#include <cstdint>
#include <math.h>

#define B_SZ   8192
#define LEADS  12
#define FIN    512
#define HID    256
#define E3     768
#define MROWS  (B_SZ * LEADS)   // 98304

// ---------------- static scratch (no allocation allowed) ----------------
__device__ float g_A[LEADS * LEADS];
__device__ __half g_qkv[(size_t)MROWS * E3];   // also reused as x16 before qkv
__device__ __half g_buf1[(size_t)MROWS * HID];
__device__ __half g_buf2[(size_t)MROWS * HID];
__device__ __half g_buf3[(size_t)MROWS * HID];

// fp16 weights, stored [N, K] K-major
__device__ __half g_W1[HID * FIN];
__device__ __half g_W2[HID * HID];
__device__ __half g_W3[HID * HID];
__device__ __half g_Iw[E3 * HID];
__device__ __half g_Ow[HID * HID];

// ---------------- helpers ----------------
__device__ __forceinline__ uint32_t smem_u32(const void* p) {
    uint32_t a;
    asm("{ .reg .u64 t; cvta.to.shared.u64 t, %1; cvt.u32.u64 %0, t; }" : "=r"(a) : "l"(p));
    return a;
}
__device__ __forceinline__ void ldsm4(uint32_t& r0, uint32_t& r1, uint32_t& r2, uint32_t& r3,
                                      uint32_t a) {
    asm volatile("ldmatrix.sync.aligned.m8n8.x4.shared.b16 {%0,%1,%2,%3}, [%4];"
                 : "=r"(r0), "=r"(r1), "=r"(r2), "=r"(r3) : "r"(a));
}
__device__ __forceinline__ void mma16816(float* c, const uint32_t* a, const uint32_t* b) {
    asm volatile("mma.sync.aligned.m16n8k16.row.col.f32.f16.f16.f32 "
                 "{%0,%1,%2,%3}, {%4,%5,%6,%7}, {%8,%9}, {%0,%1,%2,%3};"
                 : "+f"(c[0]), "+f"(c[1]), "+f"(c[2]), "+f"(c[3])
                 : "r"(a[0]), "r"(a[1]), "r"(a[2]), "r"(a[3]), "r"(b[0]), "r"(b[1]));
}
__device__ __forceinline__ void cp16(uint32_t d, const void* g) {
    asm volatile("cp.async.ca.shared.global [%0], [%1], 16;" :: "r"(d), "l"(g));
}
#define CP_COMMIT  asm volatile("cp.async.commit_group;" ::: "memory")
#define CP_WAIT(n) asm volatile("cp.async.wait_group %0;" :: "n"(n) : "memory")

// ---------------- fused prep: A_norm + weight converts + x->fp16 ----------------
#define PREP_X4   12582912                 // 50331648 / 4
#define PREP_W1   (PREP_X4 + 131072)
#define PREP_W2   (PREP_W1 + 65536)
#define PREP_W3   (PREP_W2 + 65536)
#define PREP_IW   (PREP_W3 + 196608)
#define PREP_OW   (PREP_IW + 65536)
#define PREP_THREADS PREP_OW               // 13107200
#define PREP_BLOCKS  (PREP_THREADS / 256)  // 51200

__global__ void k_prep(const float* __restrict__ x,  const float* __restrict__ W1,
                       const float* __restrict__ W2, const float* __restrict__ W3,
                       const float* __restrict__ inW, const float* __restrict__ outW,
                       __half* __restrict__ x16)
{
    size_t gid = (size_t)blockIdx.x * blockDim.x + threadIdx.x;
    if (gid == 0) {
        const int ci[18] = {0,0,1,0,1,2,0,1,1,2,6,7,8,9,10,0,1,2};
        const int cj[18] = {1,2,2,3,3,3,4,4,5,5,7,8,9,10,11,6,9,11};
        float A[12][12];
        for (int i = 0; i < 12; i++)
            for (int j = 0; j < 12; j++) A[i][j] = (i == j) ? 1.0f : 0.0f;
        for (int e = 0; e < 18; e++) { A[ci[e]][cj[e]] = 1.0f; A[cj[e]][ci[e]] = 1.0f; }
        float dinv[12];
        for (int i = 0; i < 12; i++) {
            float s = 0.0f;
            for (int j = 0; j < 12; j++) s += A[i][j];
            dinv[i] = 1.0f / sqrtf(s);
        }
        for (int i = 0; i < 12; i++)
            for (int j = 0; j < 12; j++) g_A[i * 12 + j] = dinv[i] * A[i][j] * dinv[j];
    }
    if (gid < PREP_X4) {
        float4 v = ((const float4*)x)[gid];
        ((__half2*)x16)[gid * 2]     = __floats2half2_rn(v.x, v.y);
        ((__half2*)x16)[gid * 2 + 1] = __floats2half2_rn(v.z, v.w);
        return;
    }
    if (gid < PREP_W1) {                   // W1 [512,256] -> [256,512]
        size_t l = gid - PREP_X4;
        int k = (int)(l >> 8), n = (int)(l & 255);
        g_W1[n * FIN + k] = __float2half_rn(W1[l]);
        return;
    }
    if (gid < PREP_W2) {                   // W2 [256,256] -> T
        size_t l = gid - PREP_W1;
        int k = (int)(l >> 8), n = (int)(l & 255);
        g_W2[n * HID + k] = __float2half_rn(W2[l]);
        return;
    }
    if (gid < PREP_W3) {                   // W3 [256,256] -> T
        size_t l = gid - PREP_W2;
        int k = (int)(l >> 8), n = (int)(l & 255);
        g_W3[n * HID + k] = __float2half_rn(W3[l]);
        return;
    }
    if (gid < PREP_IW) {                   // inW [768,256] already [N,K]
        size_t l = gid - PREP_W3;
        g_Iw[l] = __float2half_rn(inW[l]);
        return;
    }
    if (gid < PREP_OW) {                   // outW [256,256] already [N,K]
        size_t l = gid - PREP_IW;
        g_Ow[l] = __float2half_rn(outW[l]);
        return;
    }
}

// ---------------- GEMM core ----------------
// smem stage (half units, rows padded to SROW=40): A@0, B@5120. 4 stages.
#define SROW    40
#define STAGE_H 10240
#define STAGE_B (STAGE_H * 2)
#define NSTAGE  4
#define SMEM_BYTES (NSTAGE * STAGE_B)

struct GemmCtx {
    int lane, wm, wn;
    int arow, akblk, bn, bkblk, bntoff;
};

__device__ __forceinline__ GemmCtx make_ctx(int tid) {
    GemmCtx g;
    g.lane = tid & 31;
    int w = tid >> 5;
    g.wm = w >> 2;
    g.wn = w & 3;
    g.arow  = (g.lane & 7) | (((g.lane >> 3) & 1) << 3);
    g.akblk = (g.lane >> 4) & 1;
    int bwhich = g.lane >> 3;
    g.bn     = g.lane & 7;
    g.bkblk  = bwhich & 1;
    g.bntoff = bwhich >> 1;
    return g;
}

__device__ __forceinline__ void gemm_compute(const GemmCtx& g, uint32_t so, float c[2][4][4]) {
#pragma unroll
    for (int ks = 0; ks < 2; ks++) {
        uint32_t ah[2][4];
#pragma unroll
        for (int mt = 0; mt < 2; mt++) {
            uint32_t aoff = so + ((g.wm * 32 + mt * 16 + g.arow) * SROW + ks * 16 + g.akblk * 8) * 2;
            ldsm4(ah[mt][0], ah[mt][1], ah[mt][2], ah[mt][3], aoff);
        }
        uint32_t bh[2][4];
#pragma unroll
        for (int p = 0; p < 2; p++) {
            int nt = p * 2 + g.bntoff;
            uint32_t boff = so + (5120 + (g.wn * 32 + nt * 8 + g.bn) * SROW + ks * 16 + g.bkblk * 8) * 2;
            ldsm4(bh[p][0], bh[p][1], bh[p][2], bh[p][3], boff);
        }
#pragma unroll
        for (int mt = 0; mt < 2; mt++)
#pragma unroll
            for (int p = 0; p < 2; p++)
#pragma unroll
                for (int h = 0; h < 2; h++)
                    mma16816(c[mt][p * 2 + h], ah[mt], &bh[p][h * 2]);
    }
}

template <bool BIAS>
__global__ __launch_bounds__(512, 1) void k_hgemm(
    const __half* __restrict__ A,
    const __half* __restrict__ B,
    const float* __restrict__ bias,
    __half* __restrict__ C,
    int K, int N)
{
    extern __shared__ __half sm[];
    const int tid  = threadIdx.x;
    const int row0 = blockIdx.y * 128;
    const int col0 = blockIdx.x * 128;
    const int NC   = K >> 5;
    const uint32_t sbase = smem_u32(sm);
    GemmCtx g = make_ctx(tid);

    float c[2][4][4];
#pragma unroll
    for (int i = 0; i < 2; i++)
#pragma unroll
        for (int j = 0; j < 4; j++)
#pragma unroll
            for (int q = 0; q < 4; q++) c[i][j][q] = 0.0f;

    const int r16 = tid >> 2;
    const int q16 = (tid & 3) * 8;
    const __half* Ab = A + (size_t)(row0 + r16) * K + q16;
    const __half* Bb = B + (size_t)(col0 + r16) * K + q16;
    const uint32_t doff = (r16 * SROW + q16) * 2;

    auto cpa = [&](int cc) {
        uint32_t st = sbase + (cc & 3) * STAGE_B + doff;
        cp16(st,            Ab + cc * 32);
        cp16(st + 5120 * 2, Bb + cc * 32);
    };

    int npre = NC < 3 ? NC : 3;
    for (int s = 0; s < npre; s++) { cpa(s); CP_COMMIT; }

    for (int cc = 0; cc < NC; cc++) {
        int rem = NC - 1 - cc;
        if (rem >= 2)      CP_WAIT(2);
        else if (rem == 1) CP_WAIT(1);
        else               CP_WAIT(0);
        __syncthreads();
        gemm_compute(g, sbase + (cc & 3) * STAGE_B, c);
        if (cc + 3 < NC) { cpa(cc + 3); CP_COMMIT; }
    }

    // epilogue
#pragma unroll
    for (int mt = 0; mt < 2; mt++) {
        int row = row0 + g.wm * 32 + mt * 16 + (g.lane >> 2);
#pragma unroll
        for (int nt = 0; nt < 4; nt++) {
            int col = col0 + g.wn * 32 + nt * 8 + (g.lane & 3) * 2;
            float b0 = 0.0f, b1 = 0.0f;
            if (BIAS) { b0 = bias[col]; b1 = bias[col + 1]; }
            __half2 o0 = __floats2half2_rn(c[mt][nt][0] + b0, c[mt][nt][1] + b1);
            __half2 o1 = __floats2half2_rn(c[mt][nt][2] + b0, c[mt][nt][3] + b1);
            *(__half2*)(C + (size_t)row * N + col)       = o0;
            *(__half2*)(C + (size_t)(row + 8) * N + col) = o1;
        }
    }
}

// ---------------- lead-mix (fp16 in/out, half2) ----------------
template <bool RELU>
__global__ __launch_bounds__(256) void k_mix(
    const __half* __restrict__ T, const float* __restrict__ bias,
    __half* __restrict__ out)
{
    int b  = blockIdx.x * 2 + (threadIdx.x >> 7);
    int f2 = threadIdx.x & 127;
    const __half2* Tb = (const __half2*)(T + (size_t)b * LEADS * HID) + f2;
    float2 t[LEADS];
#pragma unroll
    for (int j = 0; j < LEADS; j++) t[j] = __half22float2(Tb[j * 128]);
    float b0 = bias[f2 * 2], b1 = bias[f2 * 2 + 1];
    __half2* Ob = (__half2*)(out + (size_t)b * LEADS * HID) + f2;
#pragma unroll
    for (int i = 0; i < LEADS; i++) {
        float ax = b0, ay = b1;
#pragma unroll
        for (int j = 0; j < LEADS; j++) {
            float w = g_A[i * 12 + j];
            ax += w * t[j].x; ay += w * t[j].y;
        }
        if (RELU) { ax = fmaxf(ax, 0.0f); ay = fmaxf(ay, 0.0f); }
        Ob[i * 128] = __floats2half2_rn(ax, ay);
    }
}

// ---------------- attention (fp16 qkv in, fp16 out) ----------------
__global__ __launch_bounds__(128) void k_attn(const __half* __restrict__ qkv,
                                              __half* __restrict__ o)
{
    __shared__ float sq[4][12 * 64];
    __shared__ float sk[4][12 * 64];
    __shared__ float sv[4][12 * 64];
    __shared__ float ss[4][12][12];

    int b    = blockIdx.x;
    int w    = threadIdx.x >> 5;
    int lane = threadIdx.x & 31;
    const __half* base = qkv + (size_t)b * LEADS * E3;

    for (int i2 = lane; i2 < 384; i2 += 32) {
        int s = i2 >> 5, d2 = (i2 & 31) * 2;
        float2 vq = __half22float2(*(const __half2*)(base + s * E3 +       w * 64 + d2));
        float2 vk = __half22float2(*(const __half2*)(base + s * E3 + 256 + w * 64 + d2));
        float2 vv = __half22float2(*(const __half2*)(base + s * E3 + 512 + w * 64 + d2));
        sq[w][s * 64 + d2] = vq.x; sq[w][s * 64 + d2 + 1] = vq.y;
        sk[w][s * 64 + d2] = vk.x; sk[w][s * 64 + d2 + 1] = vk.y;
        sv[w][s * 64 + d2] = vv.x; sv[w][s * 64 + d2 + 1] = vv.y;
    }
    __syncwarp();

    for (int st = lane; st < 144; st += 32) {
        int s = st / 12, t = st % 12;
        float acc = 0.0f;
#pragma unroll
        for (int d = 0; d < 64; d++) acc += sq[w][s * 64 + d] * sk[w][t * 64 + d];
        ss[w][s][t] = acc * 0.125f;
    }
    __syncwarp();

    if (lane < 12) {
        float mx = -1e30f;
        for (int t = 0; t < 12; t++) mx = fmaxf(mx, ss[w][lane][t]);
        float e[12], sum = 0.0f;
        for (int t = 0; t < 12; t++) { e[t] = expf(ss[w][lane][t] - mx); sum += e[t]; }
        float inv = 1.0f / sum;
        for (int t = 0; t < 12; t++) ss[w][lane][t] = e[t] * inv;
    }
    __syncwarp();

    for (int i2 = lane; i2 < 384; i2 += 32) {
        int s = i2 >> 5, d2 = (i2 & 31) * 2;
        float a0 = 0.0f, a1 = 0.0f;
#pragma unroll
        for (int t = 0; t < 12; t++) {
            float p = ss[w][s][t];
            a0 += p * sv[w][t * 64 + d2];
            a1 += p * sv[w][t * 64 + d2 + 1];
        }
        *(__half2*)(o + ((size_t)b * LEADS + s) * HID + w * 64 + d2) = __floats2half2_rn(a0, a1);
    }
}

// ---------------- residual + LayerNorm (fp16 in/out) ----------------
__global__ __launch_bounds__(256) void k_ln(
    const __half* __restrict__ h, const __half* __restrict__ a,
    const float* __restrict__ g, const float* __restrict__ bta,
    __half* __restrict__ out)
{
    int row  = blockIdx.x * 8 + (threadIdx.x >> 5);
    int lane = threadIdx.x & 31;
    const __half2* hp = (const __half2*)(h + (size_t)row * HID);
    const __half2* ap = (const __half2*)(a + (size_t)row * HID);

    float v[8];
    float sum = 0.0f;
#pragma unroll
    for (int j = 0; j < 4; j++) {
        int c2 = lane + 32 * j;
        float2 hv = __half22float2(hp[c2]);
        float2 av = __half22float2(ap[c2]);
        v[2 * j]     = hv.x + av.x;
        v[2 * j + 1] = hv.y + av.y;
        sum += v[2 * j] + v[2 * j + 1];
    }
#pragma unroll
    for (int off = 16; off; off >>= 1) sum += __shfl_xor_sync(0xFFFFFFFFu, sum, off);
    float mu = sum * (1.0f / 256.0f);

    float vs = 0.0f;
#pragma unroll
    for (int j = 0; j < 8; j++) { float d = v[j] - mu; vs += d * d; }
#pragma unroll
    for (int off = 16; off; off >>= 1) vs += __shfl_xor_sync(0xFFFFFFFFu, vs, off);
    float rs = rsqrtf(vs * (1.0f / 256.0f) + 1e-5f);

    __half2* op = (__half2*)(out + (size_t)row * HID);
#pragma unroll
    for (int j = 0; j < 4; j++) {
        int c2 = lane + 32 * j;
        float o0 = (v[2 * j]     - mu) * rs * g[c2 * 2]     + bta[c2 * 2];
        float o1 = (v[2 * j + 1] - mu) * rs * g[c2 * 2 + 1] + bta[c2 * 2 + 1];
        op[c2] = __floats2half2_rn(o0, o1);
    }
}

// ---------------- final: gcn3 mix + pooling (fp16 in, fp32 out) ----------------
__global__ __launch_bounds__(256) void k_final(
    const __half* __restrict__ T3, const float* __restrict__ b3,
    float* __restrict__ out)
{
    __shared__ float red[12][8];
    __shared__ float sw[12];
    int b = blockIdx.x, f = threadIdx.x;
    int lane = f & 31, wid = f >> 5;

    float t[LEADS];
#pragma unroll
    for (int j = 0; j < LEADS; j++)
        t[j] = __half2float(T3[((size_t)b * LEADS + j) * HID + f]);

    float bias = b3[f];
    float h3[LEADS];
#pragma unroll
    for (int i = 0; i < LEADS; i++) {
        float acc = bias;
#pragma unroll
        for (int j = 0; j < LEADS; j++) acc += g_A[i * 12 + j] * t[j];
        h3[i] = acc;
    }

#pragma unroll
    for (int i = 0; i < LEADS; i++) {
        float s = h3[i];
#pragma unroll
        for (int off = 16; off; off >>= 1) s += __shfl_xor_sync(0xFFFFFFFFu, s, off);
        if (lane == 0) red[i][wid] = s;
    }
    __syncthreads();
    if (f < 12) {
        float s = 0.0f;
        for (int w = 0; w < 8; w++) s += red[f][w];
        sw[f] = s * (1.0f / 256.0f);
    }
    __syncthreads();
    if (f == 0) {
        float mx = -1e30f;
        for (int i = 0; i < 12; i++) mx = fmaxf(mx, sw[i]);
        float e[12], sum = 0.0f;
        for (int i = 0; i < 12; i++) { e[i] = expf(sw[i] - mx); sum += e[i]; }
        float inv = 1.0f / sum;
        for (int i = 0; i < 12; i++) sw[i] = e[i] * inv;
    }
    __syncthreads();

    float ws = 0.0f, mx = -1e30f;
#pragma unroll
    for (int i = 0; i < LEADS; i++) {
        ws += h3[i] * sw[i];
        mx = fmaxf(mx, h3[i]);
    }
    out[(size_t)b * 512 + f]       = ws;
    out[(size_t)b * 512 + 256 + f] = mx;
}

// ---------------- launcher ----------------
extern "C" void kernel_launch(void* const* d_in, const int* in_sizes, int n_in,
                              void* d_out, int out_size)
{
    const float* x    = (const float*)d_in[0];
    const float* W1   = (const float*)d_in[1];
    const float* b1   = (const float*)d_in[2];
    const float* W2   = (const float*)d_in[3];
    const float* b2   = (const float*)d_in[4];
    const float* W3   = (const float*)d_in[5];
    const float* b3   = (const float*)d_in[6];
    const float* inW  = (const float*)d_in[7];
    const float* inB  = (const float*)d_in[8];
    const float* outW = (const float*)d_in[9];
    const float* outB = (const float*)d_in[10];
    const float* lng  = (const float*)d_in[11];
    const float* lnb  = (const float*)d_in[12];
    float* out = (float*)d_out;

    __half *bufQ, *buf1, *buf2, *buf3;
    cudaGetSymbolAddress((void**)&bufQ, g_qkv);
    cudaGetSymbolAddress((void**)&buf1, g_buf1);
    cudaGetSymbolAddress((void**)&buf2, g_buf2);
    cudaGetSymbolAddress((void**)&buf3, g_buf3);

    __half *w1, *w2, *w3, *iw, *ow;
    cudaGetSymbolAddress((void**)&w1, g_W1);
    cudaGetSymbolAddress((void**)&w2, g_W2);
    cudaGetSymbolAddress((void**)&w3, g_W3);
    cudaGetSymbolAddress((void**)&iw, g_Iw);
    cudaGetSymbolAddress((void**)&ow, g_Ow);

    cudaFuncSetAttribute(k_hgemm<false>, cudaFuncAttributeMaxDynamicSharedMemorySize, SMEM_BYTES);
    cudaFuncSetAttribute(k_hgemm<true>,  cudaFuncAttributeMaxDynamicSharedMemorySize, SMEM_BYTES);

    __half* x16 = bufQ;   // reuse qkv buffer as fp16-x staging (free until qkv GEMM)

    // 1: fused prep
    k_prep<<<PREP_BLOCKS, 256>>>(x, W1, W2, W3, inW, outW, x16);

    dim3 gH(2, MROWS / 128);   // N=256
    dim3 gQ(6, MROWS / 128);   // N=768

    // 2: gcn1 GEMM; 3: mix
    k_hgemm<false><<<gH, 512, SMEM_BYTES>>>(x16, w1, nullptr, buf1, FIN, HID);
    k_mix<true><<<B_SZ / 2, 256>>>(buf1, b1, buf2);

    // 4: gcn2 GEMM; 5: mix
    k_hgemm<false><<<gH, 512, SMEM_BYTES>>>(buf2, w2, nullptr, buf1, HID, HID);
    k_mix<true><<<B_SZ / 2, 256>>>(buf1, b2, buf3);     // buf3 = h2 (residual)

    // 6: qkv GEMM (ncu target)
    k_hgemm<true><<<gQ, 512, SMEM_BYTES>>>(buf3, iw, inB, bufQ, HID, E3);

    // 7: attention
    k_attn<<<B_SZ, 128>>>(bufQ, buf1);

    // 8: out_proj GEMM
    k_hgemm<true><<<gH, 512, SMEM_BYTES>>>(buf1, ow, outB, buf2, HID, HID);

    // 9: residual + LN
    k_ln<<<MROWS / 8, 256>>>(buf3, buf2, lng, lnb, buf1);

    // 10: gcn3 GEMM
    k_hgemm<false><<<gH, 512, SMEM_BYTES>>>(buf1, w3, nullptr, buf2, HID, HID);

    // 11: pooling
    k_final<<<B_SZ, 256>>>(buf2, b3, out);
}

// round 7
// speedup vs baseline: 3.0042x; 1.0920x over previous
#include <cuda_runtime.h>
#include <cuda_fp16.h>
#include <cstdint>
#include <math.h>

#define B_SZ   8192
#define LEADS  12
#define FIN    512
#define HID    256
#define E3     768
#define MROWS  (B_SZ * LEADS)   // 98304

// ---------------- static scratch (no allocation allowed) ----------------
__device__ float g_A[LEADS * LEADS];
__device__ __half g_qkv[(size_t)MROWS * E3];   // also reused as x16 before qkv
__device__ __half g_buf1[(size_t)MROWS * HID];
__device__ __half g_buf2[(size_t)MROWS * HID];
__device__ __half g_buf3[(size_t)MROWS * HID];

// fp16 weights, stored [N, K] K-major
__device__ __half g_W1[HID * FIN];
__device__ __half g_W2[HID * HID];
__device__ __half g_W3[HID * HID];
__device__ __half g_Iw[E3 * HID];
__device__ __half g_Ow[HID * HID];

// ---------------- helpers ----------------
__device__ __forceinline__ uint32_t smem_u32(const void* p) {
    uint32_t a;
    asm("{ .reg .u64 t; cvta.to.shared.u64 t, %1; cvt.u32.u64 %0, t; }" : "=r"(a) : "l"(p));
    return a;
}
__device__ __forceinline__ void ldsm4(uint32_t& r0, uint32_t& r1, uint32_t& r2, uint32_t& r3,
                                      uint32_t a) {
    asm volatile("ldmatrix.sync.aligned.m8n8.x4.shared.b16 {%0,%1,%2,%3}, [%4];"
                 : "=r"(r0), "=r"(r1), "=r"(r2), "=r"(r3) : "r"(a));
}
__device__ __forceinline__ void mma16816(float* c, const uint32_t* a, const uint32_t* b) {
    asm volatile("mma.sync.aligned.m16n8k16.row.col.f32.f16.f16.f32 "
                 "{%0,%1,%2,%3}, {%4,%5,%6,%7}, {%8,%9}, {%0,%1,%2,%3};"
                 : "+f"(c[0]), "+f"(c[1]), "+f"(c[2]), "+f"(c[3])
                 : "r"(a[0]), "r"(a[1]), "r"(a[2]), "r"(a[3]), "r"(b[0]), "r"(b[1]));
}
__device__ __forceinline__ void cp16(uint32_t d, const void* g) {
    asm volatile("cp.async.ca.shared.global [%0], [%1], 16;" :: "r"(d), "l"(g));
}
#define CP_COMMIT  asm volatile("cp.async.commit_group;" ::: "memory")
#define CP_WAIT(n) asm volatile("cp.async.wait_group %0;" :: "n"(n) : "memory")

// ---------------- fused prep: A_norm + weight converts + x->fp16 ----------------
#define PREP_X4   12582912                 // 50331648 / 4
#define PREP_W1   (PREP_X4 + 131072)
#define PREP_W2   (PREP_W1 + 65536)
#define PREP_W3   (PREP_W2 + 65536)
#define PREP_IW   (PREP_W3 + 196608)
#define PREP_OW   (PREP_IW + 65536)
#define PREP_THREADS PREP_OW
#define PREP_BLOCKS  (PREP_THREADS / 256)

__global__ void k_prep(const float* __restrict__ x,  const float* __restrict__ W1,
                       const float* __restrict__ W2, const float* __restrict__ W3,
                       const float* __restrict__ inW, const float* __restrict__ outW,
                       __half* __restrict__ x16)
{
    size_t gid = (size_t)blockIdx.x * blockDim.x + threadIdx.x;
    if (gid == 0) {
        const int ci[18] = {0,0,1,0,1,2,0,1,1,2,6,7,8,9,10,0,1,2};
        const int cj[18] = {1,2,2,3,3,3,4,4,5,5,7,8,9,10,11,6,9,11};
        float A[12][12];
        for (int i = 0; i < 12; i++)
            for (int j = 0; j < 12; j++) A[i][j] = (i == j) ? 1.0f : 0.0f;
        for (int e = 0; e < 18; e++) { A[ci[e]][cj[e]] = 1.0f; A[cj[e]][ci[e]] = 1.0f; }
        float dinv[12];
        for (int i = 0; i < 12; i++) {
            float s = 0.0f;
            for (int j = 0; j < 12; j++) s += A[i][j];
            dinv[i] = 1.0f / sqrtf(s);
        }
        for (int i = 0; i < 12; i++)
            for (int j = 0; j < 12; j++) g_A[i * 12 + j] = dinv[i] * A[i][j] * dinv[j];
    }
    if (gid < PREP_X4) {
        float4 v = ((const float4*)x)[gid];
        ((__half2*)x16)[gid * 2]     = __floats2half2_rn(v.x, v.y);
        ((__half2*)x16)[gid * 2 + 1] = __floats2half2_rn(v.z, v.w);
        return;
    }
    if (gid < PREP_W1) {
        size_t l = gid - PREP_X4;
        int k = (int)(l >> 8), n = (int)(l & 255);
        g_W1[n * FIN + k] = __float2half_rn(W1[l]);
        return;
    }
    if (gid < PREP_W2) {
        size_t l = gid - PREP_W1;
        int k = (int)(l >> 8), n = (int)(l & 255);
        g_W2[n * HID + k] = __float2half_rn(W2[l]);
        return;
    }
    if (gid < PREP_W3) {
        size_t l = gid - PREP_W2;
        int k = (int)(l >> 8), n = (int)(l & 255);
        g_W3[n * HID + k] = __float2half_rn(W3[l]);
        return;
    }
    if (gid < PREP_IW) {
        size_t l = gid - PREP_W3;
        g_Iw[l] = __float2half_rn(inW[l]);
        return;
    }
    if (gid < PREP_OW) {
        size_t l = gid - PREP_IW;
        g_Ow[l] = __float2half_rn(outW[l]);
        return;
    }
}

// ---------------- GEMM core ----------------
// Block tile 256x128, 256 threads (8 warps 4Mx2N), warp tile 64x64, BK=32.
// smem stage (half units, rows padded to SROW=40): A(256 rows)@0, B(128 rows)@10240.
// STAGE_H = 15360 half = 30720 B; 4 stages = 122880 B.
#define SROW    40
#define STAGE_H 15360
#define STAGE_B (STAGE_H * 2)
#define NSTAGE  4
#define SMEM_BYTES (NSTAGE * STAGE_B)
#define B_OFF_H 10240

struct GemmCtx {
    int lane, wm, wn;
    int arow, akblk, bn, bkblk, bntoff;
};

__device__ __forceinline__ GemmCtx make_ctx(int tid) {
    GemmCtx g;
    g.lane = tid & 31;
    int w = tid >> 5;         // 0..7
    g.wm = w >> 1;            // 0..3 (M groups of 64)
    g.wn = w & 1;             // 0..1 (N groups of 64)
    g.arow  = (g.lane & 7) | (((g.lane >> 3) & 1) << 3);
    g.akblk = (g.lane >> 4) & 1;
    int bwhich = g.lane >> 3;
    g.bn     = g.lane & 7;
    g.bkblk  = bwhich & 1;
    g.bntoff = bwhich >> 1;
    return g;
}

// per-chunk compute: warp tile 64x64 -> per ks: 4 A-ldsm4 + 4 B-ldsm4, 32 MMAs
__device__ __forceinline__ void gemm_compute(const GemmCtx& g, uint32_t so, float c[4][8][4]) {
#pragma unroll
    for (int ks = 0; ks < 2; ks++) {
        uint32_t ah[4][4];
#pragma unroll
        for (int mt = 0; mt < 4; mt++) {
            uint32_t aoff = so + ((g.wm * 64 + mt * 16 + g.arow) * SROW + ks * 16 + g.akblk * 8) * 2;
            ldsm4(ah[mt][0], ah[mt][1], ah[mt][2], ah[mt][3], aoff);
        }
        uint32_t bh[4][4];
#pragma unroll
        for (int p = 0; p < 4; p++) {
            int nt = p * 2 + g.bntoff;   // 16-col group index within warp's 64 cols
            uint32_t boff = so + (B_OFF_H + (g.wn * 64 + nt * 8 + g.bn) * SROW + ks * 16 + g.bkblk * 8) * 2;
            ldsm4(bh[p][0], bh[p][1], bh[p][2], bh[p][3], boff);
        }
#pragma unroll
        for (int mt = 0; mt < 4; mt++)
#pragma unroll
            for (int p = 0; p < 4; p++)
#pragma unroll
                for (int h = 0; h < 2; h++)
                    mma16816(c[mt][p * 2 + h], ah[mt], &bh[p][h * 2]);
    }
}

template <bool BIAS>
__global__ __launch_bounds__(256, 1) void k_hgemm(
    const __half* __restrict__ A,
    const __half* __restrict__ B,
    const float* __restrict__ bias,
    __half* __restrict__ C,
    int K, int N)
{
    extern __shared__ __half sm[];
    const int tid  = threadIdx.x;
    const int row0 = blockIdx.y * 256;
    const int col0 = blockIdx.x * 128;
    const int NC   = K >> 5;
    const uint32_t sbase = smem_u32(sm);
    GemmCtx g = make_ctx(tid);

    float c[4][8][4];
#pragma unroll
    for (int i = 0; i < 4; i++)
#pragma unroll
        for (int j = 0; j < 8; j++)
#pragma unroll
            for (int q = 0; q < 4; q++) c[i][j][q] = 0.0f;

    const int r16 = tid >> 2;          // 0..63
    const int q16 = (tid & 3) * 8;     // 0,8,16,24
    const __half* Ab = A + (size_t)(row0 + r16) * K + q16;
    const __half* Bb = B + (size_t)(col0 + r16) * K + q16;
    const uint32_t doff = (r16 * SROW + q16) * 2;

    auto cpa = [&](int cc) {
        uint32_t st = sbase + (cc & 3) * STAGE_B + doff;
        const __half* Ac = Ab + cc * 32;
        const __half* Bc = Bb + cc * 32;
#pragma unroll
        for (int u = 0; u < 4; u++)     // A: 4 x 64 rows
            cp16(st + u * 64 * SROW * 2, Ac + (size_t)(u * 64) * K);
#pragma unroll
        for (int u = 0; u < 2; u++)     // B: 2 x 64 rows
            cp16(st + (B_OFF_H + u * 64 * SROW) * 2, Bc + (size_t)(u * 64) * K);
    };

    int npre = NC < 3 ? NC : 3;
    for (int s = 0; s < npre; s++) { cpa(s); CP_COMMIT; }

    for (int cc = 0; cc < NC; cc++) {
        int rem = NC - 1 - cc;
        if (rem >= 2)      CP_WAIT(2);
        else if (rem == 1) CP_WAIT(1);
        else               CP_WAIT(0);
        __syncthreads();
        gemm_compute(g, sbase + (cc & 3) * STAGE_B, c);
        if (cc + 3 < NC) { cpa(cc + 3); CP_COMMIT; }
    }

    // epilogue: warp covers rows [wm*64, +64), cols [wn*64, +64)
#pragma unroll
    for (int mt = 0; mt < 4; mt++) {
        int row = row0 + g.wm * 64 + mt * 16 + (g.lane >> 2);
#pragma unroll
        for (int n8 = 0; n8 < 8; n8++) {
            int col = col0 + g.wn * 64 + n8 * 8 + (g.lane & 3) * 2;
            float b0 = 0.0f, b1 = 0.0f;
            if (BIAS) { b0 = bias[col]; b1 = bias[col + 1]; }
            __half2 o0 = __floats2half2_rn(c[mt][n8][0] + b0, c[mt][n8][1] + b1);
            __half2 o1 = __floats2half2_rn(c[mt][n8][2] + b0, c[mt][n8][3] + b1);
            *(__half2*)(C + (size_t)row * N + col)       = o0;
            *(__half2*)(C + (size_t)(row + 8) * N + col) = o1;
        }
    }
}

// ---------------- lead-mix (fp16 in/out, half2) ----------------
template <bool RELU>
__global__ __launch_bounds__(256) void k_mix(
    const __half* __restrict__ T, const float* __restrict__ bias,
    __half* __restrict__ out)
{
    int b  = blockIdx.x * 2 + (threadIdx.x >> 7);
    int f2 = threadIdx.x & 127;
    const __half2* Tb = (const __half2*)(T + (size_t)b * LEADS * HID) + f2;
    float2 t[LEADS];
#pragma unroll
    for (int j = 0; j < LEADS; j++) t[j] = __half22float2(Tb[j * 128]);
    float b0 = bias[f2 * 2], b1 = bias[f2 * 2 + 1];
    __half2* Ob = (__half2*)(out + (size_t)b * LEADS * HID) + f2;
#pragma unroll
    for (int i = 0; i < LEADS; i++) {
        float ax = b0, ay = b1;
#pragma unroll
        for (int j = 0; j < LEADS; j++) {
            float w = g_A[i * 12 + j];
            ax += w * t[j].x; ay += w * t[j].y;
        }
        if (RELU) { ax = fmaxf(ax, 0.0f); ay = fmaxf(ay, 0.0f); }
        Ob[i * 128] = __floats2half2_rn(ax, ay);
    }
}

// ---------------- attention (fp16 qkv in, fp16 out) ----------------
__global__ __launch_bounds__(128) void k_attn(const __half* __restrict__ qkv,
                                              __half* __restrict__ o)
{
    __shared__ float sq[4][12 * 64];
    __shared__ float sk[4][12 * 64];
    __shared__ float sv[4][12 * 64];
    __shared__ float ss[4][12][12];

    int b    = blockIdx.x;
    int w    = threadIdx.x >> 5;
    int lane = threadIdx.x & 31;
    const __half* base = qkv + (size_t)b * LEADS * E3;

    for (int i2 = lane; i2 < 384; i2 += 32) {
        int s = i2 >> 5, d2 = (i2 & 31) * 2;
        float2 vq = __half22float2(*(const __half2*)(base + s * E3 +       w * 64 + d2));
        float2 vk = __half22float2(*(const __half2*)(base + s * E3 + 256 + w * 64 + d2));
        float2 vv = __half22float2(*(const __half2*)(base + s * E3 + 512 + w * 64 + d2));
        sq[w][s * 64 + d2] = vq.x; sq[w][s * 64 + d2 + 1] = vq.y;
        sk[w][s * 64 + d2] = vk.x; sk[w][s * 64 + d2 + 1] = vk.y;
        sv[w][s * 64 + d2] = vv.x; sv[w][s * 64 + d2 + 1] = vv.y;
    }
    __syncwarp();

    for (int st = lane; st < 144; st += 32) {
        int s = st / 12, t = st % 12;
        float acc = 0.0f;
#pragma unroll
        for (int d = 0; d < 64; d++) acc += sq[w][s * 64 + d] * sk[w][t * 64 + d];
        ss[w][s][t] = acc * 0.125f;
    }
    __syncwarp();

    if (lane < 12) {
        float mx = -1e30f;
        for (int t = 0; t < 12; t++) mx = fmaxf(mx, ss[w][lane][t]);
        float e[12], sum = 0.0f;
        for (int t = 0; t < 12; t++) { e[t] = expf(ss[w][lane][t] - mx); sum += e[t]; }
        float inv = 1.0f / sum;
        for (int t = 0; t < 12; t++) ss[w][lane][t] = e[t] * inv;
    }
    __syncwarp();

    for (int i2 = lane; i2 < 384; i2 += 32) {
        int s = i2 >> 5, d2 = (i2 & 31) * 2;
        float a0 = 0.0f, a1 = 0.0f;
#pragma unroll
        for (int t = 0; t < 12; t++) {
            float p = ss[w][s][t];
            a0 += p * sv[w][t * 64 + d2];
            a1 += p * sv[w][t * 64 + d2 + 1];
        }
        *(__half2*)(o + ((size_t)b * LEADS + s) * HID + w * 64 + d2) = __floats2half2_rn(a0, a1);
    }
}

// ---------------- residual + LayerNorm (fp16 in/out) ----------------
__global__ __launch_bounds__(256) void k_ln(
    const __half* __restrict__ h, const __half* __restrict__ a,
    const float* __restrict__ g, const float* __restrict__ bta,
    __half* __restrict__ out)
{
    int row  = blockIdx.x * 8 + (threadIdx.x >> 5);
    int lane = threadIdx.x & 31;
    const __half2* hp = (const __half2*)(h + (size_t)row * HID);
    const __half2* ap = (const __half2*)(a + (size_t)row * HID);

    float v[8];
    float sum = 0.0f;
#pragma unroll
    for (int j = 0; j < 4; j++) {
        int c2 = lane + 32 * j;
        float2 hv = __half22float2(hp[c2]);
        float2 av = __half22float2(ap[c2]);
        v[2 * j]     = hv.x + av.x;
        v[2 * j + 1] = hv.y + av.y;
        sum += v[2 * j] + v[2 * j + 1];
    }
#pragma unroll
    for (int off = 16; off; off >>= 1) sum += __shfl_xor_sync(0xFFFFFFFFu, sum, off);
    float mu = sum * (1.0f / 256.0f);

    float vs = 0.0f;
#pragma unroll
    for (int j = 0; j < 8; j++) { float d = v[j] - mu; vs += d * d; }
#pragma unroll
    for (int off = 16; off; off >>= 1) vs += __shfl_xor_sync(0xFFFFFFFFu, vs, off);
    float rs = rsqrtf(vs * (1.0f / 256.0f) + 1e-5f);

    __half2* op = (__half2*)(out + (size_t)row * HID);
#pragma unroll
    for (int j = 0; j < 4; j++) {
        int c2 = lane + 32 * j;
        float o0 = (v[2 * j]     - mu) * rs * g[c2 * 2]     + bta[c2 * 2];
        float o1 = (v[2 * j + 1] - mu) * rs * g[c2 * 2 + 1] + bta[c2 * 2 + 1];
        op[c2] = __floats2half2_rn(o0, o1);
    }
}

// ---------------- final: gcn3 mix + pooling (fp16 in, fp32 out) ----------------
__global__ __launch_bounds__(256) void k_final(
    const __half* __restrict__ T3, const float* __restrict__ b3,
    float* __restrict__ out)
{
    __shared__ float red[12][8];
    __shared__ float sw[12];
    int b = blockIdx.x, f = threadIdx.x;
    int lane = f & 31, wid = f >> 5;

    float t[LEADS];
#pragma unroll
    for (int j = 0; j < LEADS; j++)
        t[j] = __half2float(T3[((size_t)b * LEADS + j) * HID + f]);

    float bias = b3[f];
    float h3[LEADS];
#pragma unroll
    for (int i = 0; i < LEADS; i++) {
        float acc = bias;
#pragma unroll
        for (int j = 0; j < LEADS; j++) acc += g_A[i * 12 + j] * t[j];
        h3[i] = acc;
    }

#pragma unroll
    for (int i = 0; i < LEADS; i++) {
        float s = h3[i];
#pragma unroll
        for (int off = 16; off; off >>= 1) s += __shfl_xor_sync(0xFFFFFFFFu, s, off);
        if (lane == 0) red[i][wid] = s;
    }
    __syncthreads();
    if (f < 12) {
        float s = 0.0f;
        for (int w = 0; w < 8; w++) s += red[f][w];
        sw[f] = s * (1.0f / 256.0f);
    }
    __syncthreads();
    if (f == 0) {
        float mx = -1e30f;
        for (int i = 0; i < 12; i++) mx = fmaxf(mx, sw[i]);
        float e[12], sum = 0.0f;
        for (int i = 0; i < 12; i++) { e[i] = expf(sw[i] - mx); sum += e[i]; }
        float inv = 1.0f / sum;
        for (int i = 0; i < 12; i++) sw[i] = e[i] * inv;
    }
    __syncthreads();

    float ws = 0.0f, mx = -1e30f;
#pragma unroll
    for (int i = 0; i < LEADS; i++) {
        ws += h3[i] * sw[i];
        mx = fmaxf(mx, h3[i]);
    }
    out[(size_t)b * 512 + f]       = ws;
    out[(size_t)b * 512 + 256 + f] = mx;
}

// ---------------- launcher ----------------
extern "C" void kernel_launch(void* const* d_in, const int* in_sizes, int n_in,
                              void* d_out, int out_size)
{
    const float* x    = (const float*)d_in[0];
    const float* W1   = (const float*)d_in[1];
    const float* b1   = (const float*)d_in[2];
    const float* W2   = (const float*)d_in[3];
    const float* b2   = (const float*)d_in[4];
    const float* W3   = (const float*)d_in[5];
    const float* b3   = (const float*)d_in[6];
    const float* inW  = (const float*)d_in[7];
    const float* inB  = (const float*)d_in[8];
    const float* outW = (const float*)d_in[9];
    const float* outB = (const float*)d_in[10];
    const float* lng  = (const float*)d_in[11];
    const float* lnb  = (const float*)d_in[12];
    float* out = (float*)d_out;

    __half *bufQ, *buf1, *buf2, *buf3;
    cudaGetSymbolAddress((void**)&bufQ, g_qkv);
    cudaGetSymbolAddress((void**)&buf1, g_buf1);
    cudaGetSymbolAddress((void**)&buf2, g_buf2);
    cudaGetSymbolAddress((void**)&buf3, g_buf3);

    __half *w1, *w2, *w3, *iw, *ow;
    cudaGetSymbolAddress((void**)&w1, g_W1);
    cudaGetSymbolAddress((void**)&w2, g_W2);
    cudaGetSymbolAddress((void**)&w3, g_W3);
    cudaGetSymbolAddress((void**)&iw, g_Iw);
    cudaGetSymbolAddress((void**)&ow, g_Ow);

    cudaFuncSetAttribute(k_hgemm<false>, cudaFuncAttributeMaxDynamicSharedMemorySize, SMEM_BYTES);
    cudaFuncSetAttribute(k_hgemm<true>,  cudaFuncAttributeMaxDynamicSharedMemorySize, SMEM_BYTES);

    __half* x16 = bufQ;   // reuse qkv buffer as fp16-x staging

    // 1: fused prep
    k_prep<<<PREP_BLOCKS, 256>>>(x, W1, W2, W3, inW, outW, x16);

    dim3 gH(2, MROWS / 256);   // N=256
    dim3 gQ(6, MROWS / 256);   // N=768

    // 2: gcn1 GEMM; 3: mix
    k_hgemm<false><<<gH, 256, SMEM_BYTES>>>(x16, w1, nullptr, buf1, FIN, HID);
    k_mix<true><<<B_SZ / 2, 256>>>(buf1, b1, buf2);

    // 4: gcn2 GEMM; 5: mix
    k_hgemm<false><<<gH, 256, SMEM_BYTES>>>(buf2, w2, nullptr, buf1, HID, HID);
    k_mix<true><<<B_SZ / 2, 256>>>(buf1, b2, buf3);     // buf3 = h2 (residual)

    // 6: qkv GEMM (ncu target)
    k_hgemm<true><<<gQ, 256, SMEM_BYTES>>>(buf3, iw, inB, bufQ, HID, E3);

    // 7: attention
    k_attn<<<B_SZ, 128>>>(bufQ, buf1);

    // 8: out_proj GEMM
    k_hgemm<true><<<gH, 256, SMEM_BYTES>>>(buf1, ow, outB, buf2, HID, HID);

    // 9: residual + LN
    k_ln<<<MROWS / 8, 256>>>(buf3, buf2, lng, lnb, buf1);

    // 10: gcn3 GEMM
    k_hgemm<false><<<gH, 256, SMEM_BYTES>>>(buf1, w3, nullptr, buf2, HID, HID);

    // 11: pooling
    k_final<<<B_SZ, 256>>>(buf2, b3, out);
}

// round 8
// speedup vs baseline: 3.0768x; 1.0242x over previous
#include <cuda_runtime.h>
#include <cuda_fp16.h>
#include <cstdint>
#include <math.h>

#define B_SZ   8192
#define LEADS  12
#define FIN    512
#define HID    256
#define E3     768
#define MROWS  (B_SZ * LEADS)   // 98304

// ---------------- static scratch ----------------
__device__ float g_A[LEADS * LEADS];
__device__ __half g_qkv[(size_t)MROWS * E3];   // also reused as x16 before qkv
__device__ __half g_buf1[(size_t)MROWS * HID];
__device__ __half g_buf2[(size_t)MROWS * HID];
__device__ __half g_buf3[(size_t)MROWS * HID];

__device__ __half g_W1[HID * FIN];
__device__ __half g_W2[HID * HID];
__device__ __half g_W3[HID * HID];
__device__ __half g_Iw[E3 * HID];
__device__ __half g_Ow[HID * HID];

// ---------------- helpers ----------------
__device__ __forceinline__ uint32_t smem_u32(const void* p) {
    uint32_t a;
    asm("{ .reg .u64 t; cvta.to.shared.u64 t, %1; cvt.u32.u64 %0, t; }" : "=r"(a) : "l"(p));
    return a;
}
__device__ __forceinline__ void ldsm4(uint32_t& r0, uint32_t& r1, uint32_t& r2, uint32_t& r3,
                                      uint32_t a) {
    asm volatile("ldmatrix.sync.aligned.m8n8.x4.shared.b16 {%0,%1,%2,%3}, [%4];"
                 : "=r"(r0), "=r"(r1), "=r"(r2), "=r"(r3) : "r"(a));
}
__device__ __forceinline__ void mma16816(float* c, const uint32_t* a, const uint32_t* b) {
    asm volatile("mma.sync.aligned.m16n8k16.row.col.f32.f16.f16.f32 "
                 "{%0,%1,%2,%3}, {%4,%5,%6,%7}, {%8,%9}, {%0,%1,%2,%3};"
                 : "+f"(c[0]), "+f"(c[1]), "+f"(c[2]), "+f"(c[3])
                 : "r"(a[0]), "r"(a[1]), "r"(a[2]), "r"(a[3]), "r"(b[0]), "r"(b[1]));
}
__device__ __forceinline__ void cp16(uint32_t d, const void* g) {
    asm volatile("cp.async.ca.shared.global [%0], [%1], 16;" :: "r"(d), "l"(g));
}
#define CP_COMMIT  asm volatile("cp.async.commit_group;" ::: "memory")
#define CP_WAIT(n) asm volatile("cp.async.wait_group %0;" :: "n"(n) : "memory")

// ---------------- fused prep ----------------
#define PREP_X4   12582912
#define PREP_W1   (PREP_X4 + 131072)
#define PREP_W2   (PREP_W1 + 65536)
#define PREP_W3   (PREP_W2 + 65536)
#define PREP_IW   (PREP_W3 + 196608)
#define PREP_OW   (PREP_IW + 65536)
#define PREP_BLOCKS  (PREP_OW / 256)

__global__ void k_prep(const float* __restrict__ x,  const float* __restrict__ W1,
                       const float* __restrict__ W2, const float* __restrict__ W3,
                       const float* __restrict__ inW, const float* __restrict__ outW,
                       __half* __restrict__ x16)
{
    size_t gid = (size_t)blockIdx.x * blockDim.x + threadIdx.x;
    if (gid == 0) {
        const int ci[18] = {0,0,1,0,1,2,0,1,1,2,6,7,8,9,10,0,1,2};
        const int cj[18] = {1,2,2,3,3,3,4,4,5,5,7,8,9,10,11,6,9,11};
        float A[12][12];
        for (int i = 0; i < 12; i++)
            for (int j = 0; j < 12; j++) A[i][j] = (i == j) ? 1.0f : 0.0f;
        for (int e = 0; e < 18; e++) { A[ci[e]][cj[e]] = 1.0f; A[cj[e]][ci[e]] = 1.0f; }
        float dinv[12];
        for (int i = 0; i < 12; i++) {
            float s = 0.0f;
            for (int j = 0; j < 12; j++) s += A[i][j];
            dinv[i] = 1.0f / sqrtf(s);
        }
        for (int i = 0; i < 12; i++)
            for (int j = 0; j < 12; j++) g_A[i * 12 + j] = dinv[i] * A[i][j] * dinv[j];
    }
    if (gid < PREP_X4) {
        float4 v = ((const float4*)x)[gid];
        ((__half2*)x16)[gid * 2]     = __floats2half2_rn(v.x, v.y);
        ((__half2*)x16)[gid * 2 + 1] = __floats2half2_rn(v.z, v.w);
        return;
    }
    if (gid < PREP_W1) {
        size_t l = gid - PREP_X4;
        int k = (int)(l >> 8), n = (int)(l & 255);
        g_W1[n * FIN + k] = __float2half_rn(W1[l]);
        return;
    }
    if (gid < PREP_W2) {
        size_t l = gid - PREP_W1;
        int k = (int)(l >> 8), n = (int)(l & 255);
        g_W2[n * HID + k] = __float2half_rn(W2[l]);
        return;
    }
    if (gid < PREP_W3) {
        size_t l = gid - PREP_W2;
        int k = (int)(l >> 8), n = (int)(l & 255);
        g_W3[n * HID + k] = __float2half_rn(W3[l]);
        return;
    }
    if (gid < PREP_IW) {
        size_t l = gid - PREP_W3;
        g_Iw[l] = __float2half_rn(inW[l]);
        return;
    }
    if (gid < PREP_OW) {
        size_t l = gid - PREP_IW;
        g_Ow[l] = __float2half_rn(outW[l]);
        return;
    }
}

// ---------------- GEMM core ----------------
// Block tile 256x128, 256 threads (8 warps 4Mx2N), warp tile 64x64, BK=64.
// smem stage (half units, rows padded to SROW=72): A(256 rows)@0, B(128 rows)@18432.
// STAGE_H = 27648 half = 55296 B; 3 stages = 165888 B.
#define SROW    72
#define B_OFF_H (256 * SROW)
#define STAGE_H (384 * SROW)
#define STAGE_B (STAGE_H * 2)
#define NSTAGE  3
#define SMEM_BYTES (NSTAGE * STAGE_B)

struct GemmCtx {
    int lane, wm, wn;
    int arow, akblk, bn, bkblk, bntoff;
};

__device__ __forceinline__ GemmCtx make_ctx(int tid) {
    GemmCtx g;
    g.lane = tid & 31;
    int w = tid >> 5;
    g.wm = w >> 1;
    g.wn = w & 1;
    g.arow  = (g.lane & 7) | (((g.lane >> 3) & 1) << 3);
    g.akblk = (g.lane >> 4) & 1;
    int bwhich = g.lane >> 3;
    g.bn     = g.lane & 7;
    g.bkblk  = bwhich & 1;
    g.bntoff = bwhich >> 1;
    return g;
}

// load A/B fragments for one 16-wide k-step (ks = 0..3)
__device__ __forceinline__ void load_frags(const GemmCtx& g, uint32_t so, int ks,
                                           uint32_t ah[4][4], uint32_t bh[4][4]) {
#pragma unroll
    for (int mt = 0; mt < 4; mt++) {
        uint32_t aoff = so + ((g.wm * 64 + mt * 16 + g.arow) * SROW + ks * 16 + g.akblk * 8) * 2;
        ldsm4(ah[mt][0], ah[mt][1], ah[mt][2], ah[mt][3], aoff);
    }
#pragma unroll
    for (int p = 0; p < 4; p++) {
        int nt = p * 2 + g.bntoff;
        uint32_t boff = so + (B_OFF_H + (g.wn * 64 + nt * 8 + g.bn) * SROW + ks * 16 + g.bkblk * 8) * 2;
        ldsm4(bh[p][0], bh[p][1], bh[p][2], bh[p][3], boff);
    }
}

__device__ __forceinline__ void do_mmas(const uint32_t ah[4][4], const uint32_t bh[4][4],
                                        float c[4][8][4]) {
#pragma unroll
    for (int mt = 0; mt < 4; mt++)
#pragma unroll
        for (int p = 0; p < 4; p++)
#pragma unroll
            for (int h = 0; h < 2; h++)
                mma16816(c[mt][p * 2 + h], ah[mt], &bh[p][h * 2]);
}

template <bool BIAS>
__global__ __launch_bounds__(256, 1) void k_hgemm(
    const __half* __restrict__ A,
    const __half* __restrict__ B,
    const float* __restrict__ bias,
    __half* __restrict__ C,
    int K, int N)
{
    extern __shared__ __half sm[];
    const int tid  = threadIdx.x;
    const int row0 = blockIdx.y * 256;
    const int col0 = blockIdx.x * 128;
    const int NC   = K >> 6;                    // BK = 64
    const uint32_t sbase = smem_u32(sm);
    GemmCtx g = make_ctx(tid);

    float c[4][8][4];
#pragma unroll
    for (int i = 0; i < 4; i++)
#pragma unroll
        for (int j = 0; j < 8; j++)
#pragma unroll
            for (int q = 0; q < 4; q++) c[i][j][q] = 0.0f;

    const int rr = tid >> 3;                    // 0..31
    const int qq = (tid & 7) * 8;               // 0..56 halves
    const __half* Ab = A + (size_t)(row0 + rr) * K + qq;
    const __half* Bb = B + (size_t)(col0 + rr) * K + qq;
    const uint32_t doff = (rr * SROW + qq) * 2;

    auto cpa = [&](int cc) {
        uint32_t st = sbase + (cc % 3) * STAGE_B + doff;
        const __half* Ac = Ab + cc * 64;
        const __half* Bc = Bb + cc * 64;
#pragma unroll
        for (int u = 0; u < 8; u++)             // A: 8 x 32 rows
            cp16(st + u * 32 * SROW * 2, Ac + (size_t)(u * 32) * K);
#pragma unroll
        for (int u = 0; u < 4; u++)             // B: 4 x 32 rows
            cp16(st + (B_OFF_H + u * 32 * SROW) * 2, Bc + (size_t)(u * 32) * K);
    };

    int npre = NC < 2 ? NC : 2;
    for (int s = 0; s < npre; s++) { cpa(s); CP_COMMIT; }

    uint32_t ah[2][4][4], bh[2][4][4];

    for (int cc = 0; cc < NC; cc++) {
        if (cc + 1 < NC) CP_WAIT(1); else CP_WAIT(0);
        __syncthreads();
        if (cc + 2 < NC) { cpa(cc + 2); CP_COMMIT; }

        uint32_t so = sbase + (cc % 3) * STAGE_B;
        load_frags(g, so, 0, ah[0], bh[0]);
#pragma unroll
        for (int ks = 0; ks < 4; ks++) {
            int cur = ks & 1;
            if (ks < 3) load_frags(g, so, ks + 1, ah[cur ^ 1], bh[cur ^ 1]);
            do_mmas(ah[cur], bh[cur], c);
        }
        __syncthreads();
    }

    // epilogue
#pragma unroll
    for (int mt = 0; mt < 4; mt++) {
        int row = row0 + g.wm * 64 + mt * 16 + (g.lane >> 2);
#pragma unroll
        for (int n8 = 0; n8 < 8; n8++) {
            int col = col0 + g.wn * 64 + n8 * 8 + (g.lane & 3) * 2;
            float b0 = 0.0f, b1 = 0.0f;
            if (BIAS) { b0 = bias[col]; b1 = bias[col + 1]; }
            __half2 o0 = __floats2half2_rn(c[mt][n8][0] + b0, c[mt][n8][1] + b1);
            __half2 o1 = __floats2half2_rn(c[mt][n8][2] + b0, c[mt][n8][3] + b1);
            *(__half2*)(C + (size_t)row * N + col)       = o0;
            *(__half2*)(C + (size_t)(row + 8) * N + col) = o1;
        }
    }
}

// ---------------- lead-mix ----------------
template <bool RELU>
__global__ __launch_bounds__(256) void k_mix(
    const __half* __restrict__ T, const float* __restrict__ bias,
    __half* __restrict__ out)
{
    int b  = blockIdx.x * 2 + (threadIdx.x >> 7);
    int f2 = threadIdx.x & 127;
    const __half2* Tb = (const __half2*)(T + (size_t)b * LEADS * HID) + f2;
    float2 t[LEADS];
#pragma unroll
    for (int j = 0; j < LEADS; j++) t[j] = __half22float2(Tb[j * 128]);
    float b0 = bias[f2 * 2], b1 = bias[f2 * 2 + 1];
    __half2* Ob = (__half2*)(out + (size_t)b * LEADS * HID) + f2;
#pragma unroll
    for (int i = 0; i < LEADS; i++) {
        float ax = b0, ay = b1;
#pragma unroll
        for (int j = 0; j < LEADS; j++) {
            float w = g_A[i * 12 + j];
            ax += w * t[j].x; ay += w * t[j].y;
        }
        if (RELU) { ax = fmaxf(ax, 0.0f); ay = fmaxf(ay, 0.0f); }
        Ob[i * 128] = __floats2half2_rn(ax, ay);
    }
}

// ---------------- attention ----------------
__global__ __launch_bounds__(128) void k_attn(const __half* __restrict__ qkv,
                                              __half* __restrict__ o)
{
    __shared__ float sq[4][12 * 64];
    __shared__ float sk[4][12 * 64];
    __shared__ float sv[4][12 * 64];
    __shared__ float ss[4][12][12];

    int b    = blockIdx.x;
    int w    = threadIdx.x >> 5;
    int lane = threadIdx.x & 31;
    const __half* base = qkv + (size_t)b * LEADS * E3;

    for (int i2 = lane; i2 < 384; i2 += 32) {
        int s = i2 >> 5, d2 = (i2 & 31) * 2;
        float2 vq = __half22float2(*(const __half2*)(base + s * E3 +       w * 64 + d2));
        float2 vk = __half22float2(*(const __half2*)(base + s * E3 + 256 + w * 64 + d2));
        float2 vv = __half22float2(*(const __half2*)(base + s * E3 + 512 + w * 64 + d2));
        sq[w][s * 64 + d2] = vq.x; sq[w][s * 64 + d2 + 1] = vq.y;
        sk[w][s * 64 + d2] = vk.x; sk[w][s * 64 + d2 + 1] = vk.y;
        sv[w][s * 64 + d2] = vv.x; sv[w][s * 64 + d2 + 1] = vv.y;
    }
    __syncwarp();

    for (int st = lane; st < 144; st += 32) {
        int s = st / 12, t = st % 12;
        float acc = 0.0f;
#pragma unroll
        for (int d = 0; d < 64; d++) acc += sq[w][s * 64 + d] * sk[w][t * 64 + d];
        ss[w][s][t] = acc * 0.125f;
    }
    __syncwarp();

    if (lane < 12) {
        float mx = -1e30f;
        for (int t = 0; t < 12; t++) mx = fmaxf(mx, ss[w][lane][t]);
        float e[12], sum = 0.0f;
        for (int t = 0; t < 12; t++) { e[t] = expf(ss[w][lane][t] - mx); sum += e[t]; }
        float inv = 1.0f / sum;
        for (int t = 0; t < 12; t++) ss[w][lane][t] = e[t] * inv;
    }
    __syncwarp();

    for (int i2 = lane; i2 < 384; i2 += 32) {
        int s = i2 >> 5, d2 = (i2 & 31) * 2;
        float a0 = 0.0f, a1 = 0.0f;
#pragma unroll
        for (int t = 0; t < 12; t++) {
            float p = ss[w][s][t];
            a0 += p * sv[w][t * 64 + d2];
            a1 += p * sv[w][t * 64 + d2 + 1];
        }
        *(__half2*)(o + ((size_t)b * LEADS + s) * HID + w * 64 + d2) = __floats2half2_rn(a0, a1);
    }
}

// ---------------- residual + LayerNorm ----------------
__global__ __launch_bounds__(256) void k_ln(
    const __half* __restrict__ h, const __half* __restrict__ a,
    const float* __restrict__ g, const float* __restrict__ bta,
    __half* __restrict__ out)
{
    int row  = blockIdx.x * 8 + (threadIdx.x >> 5);
    int lane = threadIdx.x & 31;
    const __half2* hp = (const __half2*)(h + (size_t)row * HID);
    const __half2* ap = (const __half2*)(a + (size_t)row * HID);

    float v[8];
    float sum = 0.0f;
#pragma unroll
    for (int j = 0; j < 4; j++) {
        int c2 = lane + 32 * j;
        float2 hv = __half22float2(hp[c2]);
        float2 av = __half22float2(ap[c2]);
        v[2 * j]     = hv.x + av.x;
        v[2 * j + 1] = hv.y + av.y;
        sum += v[2 * j] + v[2 * j + 1];
    }
#pragma unroll
    for (int off = 16; off; off >>= 1) sum += __shfl_xor_sync(0xFFFFFFFFu, sum, off);
    float mu = sum * (1.0f / 256.0f);

    float vs = 0.0f;
#pragma unroll
    for (int j = 0; j < 8; j++) { float d = v[j] - mu; vs += d * d; }
#pragma unroll
    for (int off = 16; off; off >>= 1) vs += __shfl_xor_sync(0xFFFFFFFFu, vs, off);
    float rs = rsqrtf(vs * (1.0f / 256.0f) + 1e-5f);

    __half2* op = (__half2*)(out + (size_t)row * HID);
#pragma unroll
    for (int j = 0; j < 4; j++) {
        int c2 = lane + 32 * j;
        float o0 = (v[2 * j]     - mu) * rs * g[c2 * 2]     + bta[c2 * 2];
        float o1 = (v[2 * j + 1] - mu) * rs * g[c2 * 2 + 1] + bta[c2 * 2 + 1];
        op[c2] = __floats2half2_rn(o0, o1);
    }
}

// ---------------- final: gcn3 mix + pooling ----------------
__global__ __launch_bounds__(256) void k_final(
    const __half* __restrict__ T3, const float* __restrict__ b3,
    float* __restrict__ out)
{
    __shared__ float red[12][8];
    __shared__ float sw[12];
    int b = blockIdx.x, f = threadIdx.x;
    int lane = f & 31, wid = f >> 5;

    float t[LEADS];
#pragma unroll
    for (int j = 0; j < LEADS; j++)
        t[j] = __half2float(T3[((size_t)b * LEADS + j) * HID + f]);

    float bias = b3[f];
    float h3[LEADS];
#pragma unroll
    for (int i = 0; i < LEADS; i++) {
        float acc = bias;
#pragma unroll
        for (int j = 0; j < LEADS; j++) acc += g_A[i * 12 + j] * t[j];
        h3[i] = acc;
    }

#pragma unroll
    for (int i = 0; i < LEADS; i++) {
        float s = h3[i];
#pragma unroll
        for (int off = 16; off; off >>= 1) s += __shfl_xor_sync(0xFFFFFFFFu, s, off);
        if (lane == 0) red[i][wid] = s;
    }
    __syncthreads();
    if (f < 12) {
        float s = 0.0f;
        for (int w = 0; w < 8; w++) s += red[f][w];
        sw[f] = s * (1.0f / 256.0f);
    }
    __syncthreads();
    if (f == 0) {
        float mx = -1e30f;
        for (int i = 0; i < 12; i++) mx = fmaxf(mx, sw[i]);
        float e[12], sum = 0.0f;
        for (int i = 0; i < 12; i++) { e[i] = expf(sw[i] - mx); sum += e[i]; }
        float inv = 1.0f / sum;
        for (int i = 0; i < 12; i++) sw[i] = e[i] * inv;
    }
    __syncthreads();

    float ws = 0.0f, mx = -1e30f;
#pragma unroll
    for (int i = 0; i < LEADS; i++) {
        ws += h3[i] * sw[i];
        mx = fmaxf(mx, h3[i]);
    }
    out[(size_t)b * 512 + f]       = ws;
    out[(size_t)b * 512 + 256 + f] = mx;
}

// ---------------- launcher ----------------
extern "C" void kernel_launch(void* const* d_in, const int* in_sizes, int n_in,
                              void* d_out, int out_size)
{
    const float* x    = (const float*)d_in[0];
    const float* W1   = (const float*)d_in[1];
    const float* b1   = (const float*)d_in[2];
    const float* W2   = (const float*)d_in[3];
    const float* b2   = (const float*)d_in[4];
    const float* W3   = (const float*)d_in[5];
    const float* b3   = (const float*)d_in[6];
    const float* inW  = (const float*)d_in[7];
    const float* inB  = (const float*)d_in[8];
    const float* outW = (const float*)d_in[9];
    const float* outB = (const float*)d_in[10];
    const float* lng  = (const float*)d_in[11];
    const float* lnb  = (const float*)d_in[12];
    float* out = (float*)d_out;

    __half *bufQ, *buf1, *buf2, *buf3;
    cudaGetSymbolAddress((void**)&bufQ, g_qkv);
    cudaGetSymbolAddress((void**)&buf1, g_buf1);
    cudaGetSymbolAddress((void**)&buf2, g_buf2);
    cudaGetSymbolAddress((void**)&buf3, g_buf3);

    __half *w1, *w2, *w3, *iw, *ow;
    cudaGetSymbolAddress((void**)&w1, g_W1);
    cudaGetSymbolAddress((void**)&w2, g_W2);
    cudaGetSymbolAddress((void**)&w3, g_W3);
    cudaGetSymbolAddress((void**)&iw, g_Iw);
    cudaGetSymbolAddress((void**)&ow, g_Ow);

    cudaFuncSetAttribute(k_hgemm<false>, cudaFuncAttributeMaxDynamicSharedMemorySize, SMEM_BYTES);
    cudaFuncSetAttribute(k_hgemm<true>,  cudaFuncAttributeMaxDynamicSharedMemorySize, SMEM_BYTES);

    __half* x16 = bufQ;

    // 1: fused prep
    k_prep<<<PREP_BLOCKS, 256>>>(x, W1, W2, W3, inW, outW, x16);

    dim3 gH(2, MROWS / 256);   // N=256
    dim3 gQ(6, MROWS / 256);   // N=768

    // 2: gcn1 GEMM; 3: mix
    k_hgemm<false><<<gH, 256, SMEM_BYTES>>>(x16, w1, nullptr, buf1, FIN, HID);
    k_mix<true><<<B_SZ / 2, 256>>>(buf1, b1, buf2);

    // 4: gcn2 GEMM; 5: mix
    k_hgemm<false><<<gH, 256, SMEM_BYTES>>>(buf2, w2, nullptr, buf1, HID, HID);
    k_mix<true><<<B_SZ / 2, 256>>>(buf1, b2, buf3);     // buf3 = h2 (residual)

    // 6: qkv GEMM (ncu target)
    k_hgemm<true><<<gQ, 256, SMEM_BYTES>>>(buf3, iw, inB, bufQ, HID, E3);

    // 7: attention
    k_attn<<<B_SZ, 128>>>(bufQ, buf1);

    // 8: out_proj GEMM
    k_hgemm<true><<<gH, 256, SMEM_BYTES>>>(buf1, ow, outB, buf2, HID, HID);

    // 9: residual + LN
    k_ln<<<MROWS / 8, 256>>>(buf3, buf2, lng, lnb, buf1);

    // 10: gcn3 GEMM
    k_hgemm<false><<<gH, 256, SMEM_BYTES>>>(buf1, w3, nullptr, buf2, HID, HID);

    // 11: pooling
    k_final<<<B_SZ, 256>>>(buf2, b3, out);
}